// round 13
// baseline (speedup 1.0000x reference)
#include <cuda_runtime.h>
#include <cuda_bf16.h>
#include <cuda_fp16.h>
#include <math.h>
#include <cstdint>

#define S_TOK  8192
#define HID    1024
#define NH     16
#define NKV    8
#define HD     128
#define SEGLEN 1024
#define QKVD   4096
#define OD     2048
#define SCALE  0.08838834764831845f

typedef unsigned long long u64;
typedef unsigned int u32;
typedef __nv_bfloat16 bf16;
typedef __half f16;

// ---------------- scratch -----------------------------------------------
__device__ f16   g_x2 [S_TOK * HID];      // x fp16
__device__ f16   g_w2 [QKVD  * HID];      // Wq|Wk|Wv fp16
__device__ bf16  g_qs [S_TOK * NH  * 256];// Q split bf16 [S][16][hi128|lo128]
__device__ bf16  g_ks [S_TOK * NKV * 256];// K split bf16 [S][8][hi128|lo128]
__device__ float g_v  [S_TOK * NKV * 96]; // V fp32 cols 0..95 [S][8][96]
__device__ f16   g_vh [S_TOK * NKV * 32]; // V cols 96..127 fp16 [S][8][32]
__device__ f16   g_o2 [S_TOK * OD];       // attn out fp16
__device__ f16   g_wo2[HID * OD];         // Wo fp16

// ---------------- helpers ------------------------------------------------
__device__ __forceinline__ u64 pack2(float a, float b) {
    u64 r; asm("mov.b64 %0,{%1,%2};" : "=l"(r) : "f"(a), "f"(b)); return r;
}
__device__ __forceinline__ void unpack2(u64 v, float& a, float& b) {
    asm("mov.b64 {%0,%1},%2;" : "=f"(a), "=f"(b) : "l"(v));
}
__device__ __forceinline__ void fma2(u64& c, u64 a, u64 b) {
    asm("fma.rn.f32x2 %0,%1,%2,%3;" : "=l"(c) : "l"(a), "l"(b), "l"(c));
}
__device__ __forceinline__ u64 mul2(u64 a, u64 b) {
    u64 r; asm("mul.rn.f32x2 %0,%1,%2;" : "=l"(r) : "l"(a), "l"(b)); return r;
}
__device__ __forceinline__ u32 s2u(const void* p) {
    u32 a; asm("{ .reg .u64 t; cvta.to.shared.u64 t,%1; cvt.u32.u64 %0,t; }"
               : "=r"(a) : "l"(p));
    return a;
}
__device__ __forceinline__ void cp16(u32 dst, const void* src) {
    asm volatile("cp.async.cg.shared.global [%0],[%1],16;" :: "r"(dst), "l"(src));
}
__device__ __forceinline__ void cp_commit() {
    asm volatile("cp.async.commit_group;" ::: "memory");
}
__device__ __forceinline__ void ldsm_x4(u32* r, u32 addr) {
    asm volatile("ldmatrix.sync.aligned.m8n8.x4.shared.b16 {%0,%1,%2,%3},[%4];"
                 : "=r"(r[0]), "=r"(r[1]), "=r"(r[2]), "=r"(r[3]) : "r"(addr));
}
__device__ __forceinline__ void ldsm_x4_t(u32* r, u32 addr) {
    asm volatile("ldmatrix.sync.aligned.m8n8.x4.trans.shared.b16 {%0,%1,%2,%3},[%4];"
                 : "=r"(r[0]), "=r"(r[1]), "=r"(r[2]), "=r"(r[3]) : "r"(addr));
}
__device__ __forceinline__ void mma_bf16(float* d, const u32* a, const u32* b) {
    asm volatile(
        "mma.sync.aligned.m16n8k16.row.col.f32.bf16.bf16.f32 "
        "{%0,%1,%2,%3},{%4,%5,%6,%7},{%8,%9},{%0,%1,%2,%3};"
        : "+f"(d[0]), "+f"(d[1]), "+f"(d[2]), "+f"(d[3])
        : "r"(a[0]), "r"(a[1]), "r"(a[2]), "r"(a[3]), "r"(b[0]), "r"(b[1]));
}
__device__ __forceinline__ void mma_f16(float* d, const u32* a, const u32* b) {
    asm volatile(
        "mma.sync.aligned.m16n8k16.row.col.f32.f16.f16.f32 "
        "{%0,%1,%2,%3},{%4,%5,%6,%7},{%8,%9},{%0,%1,%2,%3};"
        : "+f"(d[0]), "+f"(d[1]), "+f"(d[2]), "+f"(d[3])
        : "r"(a[0]), "r"(a[1]), "r"(a[2]), "r"(a[3]), "r"(b[0]), "r"(b[1]));
}
__device__ __forceinline__ u32 packh2(float a, float b) {
    u32 r; asm("cvt.rn.f16x2.f32 %0,%1,%2;" : "=r"(r) : "f"(b), "f"(a));
    return r;
}

// ---------------------------------------------------------------------------
// merged fp16 conversion: x, Wq, Wk, Wv, Wo in one launch (8 elems/thread)
// grid = 4096 + 1024 + 512 + 512 + 1024 = 7168 blocks
// ---------------------------------------------------------------------------
__global__ __launch_bounds__(256) void cvt_all(
    const float* __restrict__ x,  const float* __restrict__ Wq,
    const float* __restrict__ Wk, const float* __restrict__ Wv,
    const float* __restrict__ Wo,
    f16* __restrict__ x2, f16* __restrict__ w2, f16* __restrict__ wo2)
{
    int b = blockIdx.x;
    const float* src; f16* dst; int base;
    if (b < 4096)      { src = x;  dst = x2;                          base = b; }
    else if (b < 5120) { src = Wq; dst = w2;                          base = b - 4096; }
    else if (b < 5632) { src = Wk; dst = w2 + (size_t)2048 * HID;     base = b - 5120; }
    else if (b < 6144) { src = Wv; dst = w2 + (size_t)3072 * HID;     base = b - 5632; }
    else               { src = Wo; dst = wo2;                         base = b - 6144; }
    size_t i = ((size_t)base * 256 + threadIdx.x) * 8;
    float4 v0 = *(const float4*)(src + i);
    float4 v1 = *(const float4*)(src + i + 4);
    uint4 o;
    o.x = packh2(v0.x, v0.y); o.y = packh2(v0.z, v0.w);
    o.z = packh2(v1.x, v1.y); o.w = packh2(v1.z, v1.w);
    *(uint4*)(dst + i) = o;
}

// ---------------------------------------------------------------------------
// mma.sync GEMM (proven mainloop): C = A[M,Kp] f16 @ B[N,Kp]^T f16
// fuse==0: plain fp32 epilogue. fuse==1: QKV epilogue (norm+rope / V stores).
// ---------------------------------------------------------------------------
#define GSTAGE 32768
#define GEMM_SMEM (3 * GSTAGE)

__global__ __launch_bounds__(256) void gemm_mma(
    const f16* __restrict__ A, const f16* __restrict__ B,
    float* __restrict__ C, int N, int Kp, int fuse,
    bf16* __restrict__ qs, bf16* __restrict__ ks,
    float* __restrict__ vout, f16* __restrict__ vhout,
    const float* __restrict__ cosT, const float* __restrict__ sinT,
    const float* __restrict__ qw, const float* __restrict__ kw)
{
    extern __shared__ char smc[];
    const u32 smb = s2u(smc);
    const int tid = threadIdx.x;
    const int warp = tid >> 5, lane = tid & 31;
    const int wM = warp >> 2, wN = warp & 3;
    const int m0 = blockIdx.y << 7, n0 = blockIdx.x << 7;
    const int chunks = Kp >> 6;

    const f16* Ag = A + (size_t)m0 * Kp;
    const f16* Bg = B + (size_t)n0 * Kp;

    float acc[4][4][4];
#pragma unroll
    for (int a = 0; a < 4; a++)
#pragma unroll
        for (int b = 0; b < 4; b++)
#pragma unroll
            for (int c = 0; c < 4; c++) acc[a][b][c] = 0.f;

    auto load_stage = [&](int st, int ch) {
        u32 sa = smb + st * GSTAGE;
        u32 sb = sa + 16384;
#pragma unroll
        for (int j = 0; j < 4; j++) {
            int q = tid + j * 256;
            int r = q >> 3, c = q & 7;
            cp16(sa + r * 128 + ((c ^ (r & 7)) << 4),
                 Ag + (size_t)r * Kp + ch * 64 + c * 8);
        }
#pragma unroll
        for (int j = 0; j < 4; j++) {
            int q = tid + j * 256;
            int r = q >> 3, c = q & 7;
            cp16(sb + r * 128 + ((c ^ (r & 7)) << 4),
                 Bg + (size_t)r * Kp + ch * 64 + c * 8);
        }
        cp_commit();
    };

    load_stage(0, 0);
    load_stage(1, 1);

    for (int i = 0; i < chunks; i++) {
        int s = i % 3;
        asm volatile("cp.async.wait_group 1;" ::: "memory");
        __syncthreads();
        if (i + 2 < chunks) load_stage((i + 2) % 3, i + 2);
        else cp_commit();

        u32 sa = smb + s * GSTAGE;
        u32 sb = sa + 16384;
#pragma unroll
        for (int kk = 0; kk < 4; kk++) {
            u32 afr[4][4], bfr[2][4];
#pragma unroll
            for (int mt = 0; mt < 4; mt++) {
                int row = wM * 64 + mt * 16 + (lane & 15);
                int ch = kk * 2 + (lane >> 4);
                ldsm_x4(afr[mt], sa + row * 128 + ((ch ^ (row & 7)) << 4));
            }
#pragma unroll
            for (int p = 0; p < 2; p++) {
                int row = wN * 32 + p * 16 + ((lane >> 4) << 3) + (lane & 7);
                int ch = kk * 2 + ((lane >> 3) & 1);
                ldsm_x4(bfr[p], sb + row * 128 + ((ch ^ (row & 7)) << 4));
            }
#pragma unroll
            for (int mt = 0; mt < 4; mt++)
#pragma unroll
                for (int nt = 0; nt < 4; nt++)
                    mma_f16(acc[mt][nt], afr[mt], &bfr[nt >> 1][(nt & 1) * 2]);
        }
    }

    const int g = lane >> 2, t = lane & 3;

    if (!fuse) {
#pragma unroll
        for (int mt = 0; mt < 4; mt++) {
            int r0 = m0 + wM * 64 + mt * 16 + g;
#pragma unroll
            for (int nt = 0; nt < 4; nt++) {
                int cc = n0 + wN * 32 + nt * 8 + t * 2;
                *(float2*)(C + (size_t)r0 * N + cc) =
                    make_float2(acc[mt][nt][0], acc[mt][nt][1]);
                *(float2*)(C + (size_t)(r0 + 8) * N + cc) =
                    make_float2(acc[mt][nt][2], acc[mt][nt][3]);
            }
        }
        return;
    }

    const int nb = blockIdx.x;   // 0..15 q, 16..23 k, 24..31 v
    if (nb >= 24) {
        int head = nb - 24;
        if (wN < 3) {   // cols 0..95 -> fp32 [S][8][96]
            int vc0 = head * 96;
#pragma unroll
            for (int mt = 0; mt < 4; mt++) {
                int r0 = m0 + wM * 64 + mt * 16 + g;
#pragma unroll
                for (int nt = 0; nt < 4; nt++) {
                    int cc = vc0 + wN * 32 + nt * 8 + t * 2;
                    *(float2*)(vout + (size_t)r0 * (NKV * 96) + cc) =
                        make_float2(acc[mt][nt][0], acc[mt][nt][1]);
                    *(float2*)(vout + (size_t)(r0 + 8) * (NKV * 96) + cc) =
                        make_float2(acc[mt][nt][2], acc[mt][nt][3]);
                }
            }
        } else {        // cols 96..127 -> fp16 [S][8][32]
#pragma unroll
            for (int mt = 0; mt < 4; mt++) {
                int r0 = m0 + wM * 64 + mt * 16 + g;
#pragma unroll
                for (int nt = 0; nt < 4; nt++) {
                    int sc = nt * 8 + t * 2;
                    *(u32*)(vhout + ((size_t)r0 * NKV + head) * 32 + sc) =
                        packh2(acc[mt][nt][0], acc[mt][nt][1]);
                    *(u32*)(vhout + ((size_t)(r0 + 8) * NKV + head) * 32 + sc) =
                        packh2(acc[mt][nt][2], acc[mt][nt][3]);
                }
            }
        }
        return;
    }

    // q/k block: fused RMSNorm + RoPE (stage tile through smem)
    float* Cs = (float*)smc;
    __syncthreads();
#pragma unroll
    for (int mt = 0; mt < 4; mt++) {
        int rl = wM * 64 + mt * 16 + g;
#pragma unroll
        for (int nt = 0; nt < 4; nt++) {
            int cl = wN * 32 + nt * 8 + t * 2;
            *(float2*)&Cs[rl * 132 + cl]       = make_float2(acc[mt][nt][0], acc[mt][nt][1]);
            *(float2*)&Cs[(rl + 8) * 132 + cl] = make_float2(acc[mt][nt][2], acc[mt][nt][3]);
        }
    }
    __syncthreads();

    const bool isQ = (nb < 16);
    const float* w = isQ ? qw : kw;
    const float4 wv = *(const float4*)(w + lane * 4);
    const float sgn = (lane < 16) ? -1.0f : 1.0f;
    const size_t tstream = (lane < 16) ? (size_t)0 : (size_t)S_TOK * HD;

#pragma unroll 4
    for (int rr = 0; rr < 16; rr++) {
        int row = warp * 16 + rr;
        int s = m0 + row;

        float4 x = *(const float4*)&Cs[row * 132 + lane * 4];
        float ss = x.x * x.x + x.y * x.y + x.z * x.z + x.w * x.w;
#pragma unroll
        for (int m = 16; m > 0; m >>= 1) ss += __shfl_xor_sync(0xffffffffu, ss, m);
        float r = rsqrtf(ss * (1.0f / 128.0f) + 1e-6f);

        float xn0 = x.x * r * wv.x, xn1 = x.y * r * wv.y;
        float xn2 = x.z * r * wv.z, xn3 = x.w * r * wv.w;

        float p0 = __shfl_xor_sync(0xffffffffu, xn0, 16);
        float p1 = __shfl_xor_sync(0xffffffffu, xn1, 16);
        float p2 = __shfl_xor_sync(0xffffffffu, xn2, 16);
        float p3 = __shfl_xor_sync(0xffffffffu, xn3, 16);

        size_t toff = tstream + (size_t)s * HD + lane * 4;
        float4 cv = *(const float4*)(cosT + toff);
        float4 sv = *(const float4*)(sinT + toff);

        float ov[4];
        ov[0] = xn0 * cv.x + sgn * p0 * sv.x;
        ov[1] = xn1 * cv.y + sgn * p1 * sv.y;
        ov[2] = xn2 * cv.z + sgn * p2 * sv.z;
        ov[3] = xn3 * cv.w + sgn * p3 * sv.w;

        u64 hp = 0, lp = 0;
#pragma unroll
        for (int j = 0; j < 4; j++) {
            bf16 hb = __float2bfloat16(ov[j]);
            bf16 lb = __float2bfloat16(ov[j] - __bfloat162float(hb));
            hp |= (u64)(*(unsigned short*)&hb) << (16 * j);
            lp |= (u64)(*(unsigned short*)&lb) << (16 * j);
        }
        bf16* dst = isQ ? (qs + ((size_t)s * NH + nb) * 256)
                        : (ks + ((size_t)s * NKV + (nb - 16)) * 256);
        *(u64*)(dst + lane * 4)       = hp;
        *(u64*)(dst + 128 + lane * 4) = lp;
    }
}

// ---------------------------------------------------------------------------
// Warp-specialized hybrid attention, 32-key chunks, fp16 P, 2 CTAs/SM.
//   S-warps (0-3): bf16 3-term scores + softmax + fp16 tensor PV (cols 96-127)
//   V-warps (4-7): fp32 f32x2 PV (cols 0-95)
// smem: Q 32K | K 2x16K | V96 2x12K | P(fp16) 2x4.5K | A 0.5K | L 0.25K | VSL 2x2.5K
// ---------------------------------------------------------------------------
#define NCH 32
#define AQS 0
#define AKS 32768
#define AVS 65536
#define APF 90112
#define AAF 99328
#define ALF 99840
#define VSLO 100096
#define ATT_SMEM 105216
#define VSTR96 (NKV * 96)   // 768

__global__ __launch_bounds__(256, 2) void attn_tc(
    const bf16* __restrict__ qs, const bf16* __restrict__ ks,
    const float* __restrict__ v, const f16* __restrict__ vh,
    f16* __restrict__ o2)
{
    extern __shared__ char sm[];
    const u32 smb = s2u(sm);
    float* Af = (float*)(sm + AAF);
    float* Lf = (float*)(sm + ALF);

    const int tid = threadIdx.x;
    const int warp = tid >> 5, lane = tid & 31;
    const bool isS = warp < 4;
    const int qt = blockIdx.x, seg = blockIdx.y, h = blockIdx.z;
    const int hkv = h >> 1;

    const bf16* Qg = qs + ((size_t)(seg * SEGLEN + qt * 64) * NH + h) * 256;
    const bf16* Kg = ks + ((size_t)(seg * SEGLEN) * NKV + hkv) * 256;
    const float* Vg = v + (size_t)(seg * SEGLEN) * VSTR96 + hkv * 96;
    const f16* Vhg = vh + ((size_t)(seg * SEGLEN) * NKV + hkv) * 32;

    // ---- prologue ----
#pragma unroll
    for (int j = 0; j < 8; j++) {
        int q = tid + j * 256;
        int r = q >> 5, c = q & 31;
        cp16(smb + AQS + r * 512 + ((c ^ (r & 7)) << 4),
             Qg + (size_t)r * (NH * 256) + c * 8);
    }
    cp_commit();
    if (isS) {
#pragma unroll
        for (int j = 0; j < 8; j++) {           // K chunk 0: 32 rows x 512B
            int q = tid + j * 128;
            int r = q >> 5, c = q & 31;
            cp16(smb + AKS + r * 512 + ((c ^ (r & 7)) << 4),
                 Kg + (size_t)r * (NKV * 256) + c * 8);
        }
        {                                        // VSL chunk 0: 32 rows x 64B
            int q = tid;
            int r = q >> 2, sg = q & 3;
            cp16(smb + VSLO + r * 80 + sg * 16,
                 Vhg + (size_t)r * (NKV * 32) + sg * 8);
        }
        cp_commit();
    } else {
        int vt = tid - 128;
#pragma unroll
        for (int j = 0; j < 6; j++) {           // V chunk 0: 32 rows x 384B
            int q = vt + j * 128;
            int r = q / 24, c = q % 24;
            cp16(smb + AVS + r * 384 + c * 16, Vg + (size_t)r * VSTR96 + c * 4);
        }
        cp_commit();
    }

    const int g = lane >> 2, t = lane & 3;
    float m0 = -INFINITY, m1 = -INFINITY, l0 = 0.f, l1 = 0.f;
    float osl[4][4];
#pragma unroll
    for (int n = 0; n < 4; n++)
#pragma unroll
        for (int c = 0; c < 4; c++) osl[n][c] = 0.f;

    u64 O2[8][3];
#pragma unroll
    for (int i = 0; i < 8; i++)
#pragma unroll
        for (int j = 0; j < 3; j++) O2[i][j] = 0ULL;
    const int vt = tid - 128;
    const int tx = vt & 15, ty = vt >> 4;

    for (int it = 0; it <= NCH; it++) {
        asm volatile("cp.async.wait_group 0;" ::: "memory");
        __syncthreads();

        if (isS && it < NCH) {
            if (it + 1 < NCH) {
                u32 kd = smb + AKS + ((it + 1) & 1) * 16384;
#pragma unroll
                for (int j = 0; j < 8; j++) {
                    int q = tid + j * 128;
                    int r = q >> 5, c = q & 31;
                    cp16(kd + r * 512 + ((c ^ (r & 7)) << 4),
                         Kg + (size_t)((it + 1) * 32 + r) * (NKV * 256) + c * 8);
                }
                u32 vsd = smb + VSLO + ((it + 1) & 1) * 2560;
                {
                    int q = tid;
                    int r = q >> 2, sg = q & 3;
                    cp16(vsd + r * 80 + sg * 16,
                         Vhg + (size_t)((it + 1) * 32 + r) * (NKV * 32) + sg * 8);
                }
                cp_commit();
            }
            u32 kb = smb + AKS + (it & 1) * 16384;
            float acc[4][4];
#pragma unroll
            for (int n = 0; n < 4; n++)
#pragma unroll
                for (int c = 0; c < 4; c++) acc[n][c] = 0.f;

            const int ABASE[3] = {0, 16, 0};
            const int BBASE[3] = {0, 0, 16};
#pragma unroll
            for (int p = 0; p < 3; p++) {
#pragma unroll
                for (int k = 0; k < 8; k++) {
                    u32 afr[4], bfr[2][4];
                    int ar = warp * 16 + (lane & 15);
                    int ac = ABASE[p] + 2 * k + (lane >> 4);
                    ldsm_x4(afr, smb + AQS + ar * 512 + ((ac ^ (ar & 7)) << 4));
#pragma unroll
                    for (int pg = 0; pg < 2; pg++) {
                        int br = pg * 16 + ((lane >> 4) << 3) + (lane & 7);
                        int bc = BBASE[p] + 2 * k + ((lane >> 3) & 1);
                        ldsm_x4(bfr[pg], kb + br * 512 + ((bc ^ (br & 7)) << 4));
                    }
#pragma unroll
                    for (int nt = 0; nt < 4; nt++)
                        mma_bf16(acc[nt], afr, &bfr[nt >> 1][(nt & 1) * 2]);
                }
            }
            // ---- online softmax ----
            float mx0 = -INFINITY, mx1 = -INFINITY;
#pragma unroll
            for (int n = 0; n < 4; n++) {
#pragma unroll
                for (int c = 0; c < 4; c++) acc[n][c] *= SCALE;
                mx0 = fmaxf(mx0, fmaxf(acc[n][0], acc[n][1]));
                mx1 = fmaxf(mx1, fmaxf(acc[n][2], acc[n][3]));
            }
            mx0 = fmaxf(mx0, __shfl_xor_sync(0xffffffffu, mx0, 1));
            mx0 = fmaxf(mx0, __shfl_xor_sync(0xffffffffu, mx0, 2));
            mx1 = fmaxf(mx1, __shfl_xor_sync(0xffffffffu, mx1, 1));
            mx1 = fmaxf(mx1, __shfl_xor_sync(0xffffffffu, mx1, 2));
            float mn0 = fmaxf(m0, mx0), mn1 = fmaxf(m1, mx1);
            float a0 = __expf(m0 - mn0), a1 = __expf(m1 - mn1);
            m0 = mn0; m1 = mn1;
            float s0 = 0.f, s1 = 0.f;
#pragma unroll
            for (int n = 0; n < 4; n++) {
                acc[n][0] = __expf(acc[n][0] - mn0); s0 += acc[n][0];
                acc[n][1] = __expf(acc[n][1] - mn0); s0 += acc[n][1];
                acc[n][2] = __expf(acc[n][2] - mn1); s1 += acc[n][2];
                acc[n][3] = __expf(acc[n][3] - mn1); s1 += acc[n][3];
            }
            s0 += __shfl_xor_sync(0xffffffffu, s0, 1);
            s0 += __shfl_xor_sync(0xffffffffu, s0, 2);
            s1 += __shfl_xor_sync(0xffffffffu, s1, 1);
            s1 += __shfl_xor_sync(0xffffffffu, s1, 2);
            l0 = l0 * a0 + s0;
            l1 = l1 * a1 + s1;

            int r0 = warp * 16 + g, r1 = r0 + 8;
            char* Pb = sm + APF + (it & 1) * 4608;
#pragma unroll
            for (int n = 0; n < 4; n++) {
                *(u32*)(Pb + r0 * 72 + (n * 8 + t * 2) * 2) = packh2(acc[n][0], acc[n][1]);
                *(u32*)(Pb + r1 * 72 + (n * 8 + t * 2) * 2) = packh2(acc[n][2], acc[n][3]);
            }
            if (t == 0) {
                Af[(it & 1) * 64 + r0] = a0;
                Af[(it & 1) * 64 + r1] = a1;
                if (it == NCH - 1) { Lf[r0] = l0; Lf[r1] = l1; }
            }

            // ---- tensor PV slice: cols 96..127 ----
#pragma unroll
            for (int n = 0; n < 4; n++) {
                osl[n][0] *= a0; osl[n][1] *= a0;
                osl[n][2] *= a1; osl[n][3] *= a1;
            }
            u32 vsb = smb + VSLO + (it & 1) * 2560;
#pragma unroll
            for (int kk = 0; kk < 2; kk++) {
                u32 pa[4];
                pa[0] = packh2(acc[2 * kk][0],     acc[2 * kk][1]);
                pa[1] = packh2(acc[2 * kk][2],     acc[2 * kk][3]);
                pa[2] = packh2(acc[2 * kk + 1][0], acc[2 * kk + 1][1]);
                pa[3] = packh2(acc[2 * kk + 1][2], acc[2 * kk + 1][3]);
                u32 vb0[4], vb1[4];
                u32 base = vsb + (kk * 16 + (lane & 15)) * 80 + ((lane >> 4) << 4);
                ldsm_x4_t(vb0, base);
                ldsm_x4_t(vb1, base + 32);
                mma_f16(osl[0], pa, vb0);
                mma_f16(osl[1], pa, vb0 + 2);
                mma_f16(osl[2], pa, vb1);
                mma_f16(osl[3], pa, vb1 + 2);
            }
        }

        if (!isS && it > 0) {
            int j = it - 1;
            if (it < NCH) {
                u32 vd = smb + AVS + (it & 1) * 12288;
#pragma unroll
                for (int jj = 0; jj < 6; jj++) {
                    int q = vt + jj * 128;
                    int r = q / 24, c = q % 24;
                    cp16(vd + r * 384 + c * 16,
                         Vg + (size_t)(it * 32 + r) * VSTR96 + c * 4);
                }
                cp_commit();
            }
            const char* Pb = sm + APF + (j & 1) * 4608;
            const char* Vb = sm + AVS + (j & 1) * 12288;
#pragma unroll
            for (int ii = 0; ii < 8; ii++) {
                float a = Af[(j & 1) * 64 + ty * 8 + ii];
                u64 ad = pack2(a, a);
#pragma unroll
                for (int c = 0; c < 3; c++) O2[ii][c] = mul2(O2[ii][c], ad);
            }
#pragma unroll 2
            for (int j4 = 0; j4 < 8; j4++) {
                float pv[8][4];
#pragma unroll
                for (int ii = 0; ii < 8; ii++) {
                    uint2 u = *(const uint2*)(Pb + (ty * 8 + ii) * 72 + j4 * 8);
                    float2 f01 = __half22float2(*(__half2*)&u.x);
                    float2 f23 = __half22float2(*(__half2*)&u.y);
                    pv[ii][0] = f01.x; pv[ii][1] = f01.y;
                    pv[ii][2] = f23.x; pv[ii][3] = f23.y;
                }
#pragma unroll
                for (int e = 0; e < 4; e++) {
                    const u64* vr = (const u64*)(Vb + ((j4 * 4 + e) * 96 + tx * 6) * 4);
                    u64 v0 = vr[0], v1 = vr[1], v2 = vr[2];
#pragma unroll
                    for (int ii = 0; ii < 8; ii++) {
                        u64 pd = pack2(pv[ii][e], pv[ii][e]);
                        fma2(O2[ii][0], pd, v0);
                        fma2(O2[ii][1], pd, v1);
                        fma2(O2[ii][2], pd, v2);
                    }
                }
            }
        }
    }

    if (isS) {
        float inv0 = 1.0f / l0, inv1 = 1.0f / l1;
        int gr0 = seg * SEGLEN + qt * 64 + warp * 16 + g;
#pragma unroll
        for (int n = 0; n < 4; n++) {
            int col = h * HD + 96 + n * 8 + t * 2;
            *(u32*)(o2 + (size_t)gr0 * OD + col) =
                packh2(osl[n][0] * inv0, osl[n][1] * inv0);
            *(u32*)(o2 + (size_t)(gr0 + 8) * OD + col) =
                packh2(osl[n][2] * inv1, osl[n][3] * inv1);
        }
    } else {
#pragma unroll
        for (int ii = 0; ii < 8; ii++) {
            int row = ty * 8 + ii;
            float inv = 1.0f / Lf[row];
            f16* orow = o2 + (size_t)(seg * SEGLEN + qt * 64 + row) * OD + h * HD + tx * 6;
#pragma unroll
            for (int c = 0; c < 3; c++) {
                float lo, hi; unpack2(O2[ii][c], lo, hi);
                *(u32*)(orow + 2 * c) = packh2(lo * inv, hi * inv);
            }
        }
    }
}

// ---------------------------------------------------------------------------
extern "C" void kernel_launch(void* const* d_in, const int* in_sizes, int n_in,
                              void* d_out, int out_size)
{
    const float* x    = (const float*)d_in[0];
    const float* cosT = (const float*)d_in[2];
    const float* sinT = (const float*)d_in[3];
    const float* Wq   = (const float*)d_in[4];
    const float* Wk   = (const float*)d_in[5];
    const float* Wv   = (const float*)d_in[6];
    const float* Wo   = (const float*)d_in[7];
    const float* qw   = (const float*)d_in[8];
    const float* kw   = (const float*)d_in[9];
    float* out = (float*)d_out;

    f16 *x2, *w2, *o2, *wo2, *vhp;
    bf16 *qsp, *ksp;
    float *vp;
    cudaGetSymbolAddress((void**)&x2,  g_x2);
    cudaGetSymbolAddress((void**)&w2,  g_w2);
    cudaGetSymbolAddress((void**)&o2,  g_o2);
    cudaGetSymbolAddress((void**)&wo2, g_wo2);
    cudaGetSymbolAddress((void**)&qsp, g_qs);
    cudaGetSymbolAddress((void**)&ksp, g_ks);
    cudaGetSymbolAddress((void**)&vp,  g_v);
    cudaGetSymbolAddress((void**)&vhp, g_vh);

    cudaFuncSetAttribute(gemm_mma,
        cudaFuncAttributeMaxDynamicSharedMemorySize, GEMM_SMEM);
    cudaFuncSetAttribute(attn_tc,
        cudaFuncAttributeMaxDynamicSharedMemorySize, ATT_SMEM);

    // launch 0: all conversions in one kernel
    cvt_all<<<7168, 256>>>(x, Wq, Wk, Wv, Wo, x2, w2, wo2);

    // launch 1: QKV projection (fp16) with fused RMSNorm+RoPE / V-split epilogue
    gemm_mma<<<dim3(QKVD / 128, S_TOK / 128), 256, GEMM_SMEM>>>(
        x2, w2, nullptr, QKVD, HID, 1, qsp, ksp, vp, vhp, cosT, sinT, qw, kw);

    // launch 2: hybrid attention (32-key chunks, 2 CTAs/SM) -> fp16 output
    attn_tc<<<dim3(16, 8, 16), 256, ATT_SMEM>>>(qsp, ksp, vp, vhp, o2);

    // launch 3: output projection (fp16) -> d_out
    gemm_mma<<<dim3(HID / 128, S_TOK / 128), 256, GEMM_SMEM>>>(
        o2, wo2, out, HID, OD, 0, nullptr, nullptr, nullptr, nullptr,
        nullptr, nullptr, nullptr, nullptr);
}

// round 14
// speedup vs baseline: 1.0644x; 1.0644x over previous
#include <cuda_runtime.h>
#include <cuda_bf16.h>
#include <cuda_fp16.h>
#include <math.h>
#include <cstdint>

#define S_TOK  8192
#define HID    1024
#define NH     16
#define NKV    8
#define HD     128
#define SEGLEN 1024
#define QKVD   4096
#define OD     2048
#define SCALE  0.08838834764831845f

typedef unsigned long long u64;
typedef unsigned int u32;
typedef __nv_bfloat16 bf16;
typedef __half f16;

// ---------------- scratch -----------------------------------------------
__device__ f16   g_x2 [S_TOK * HID];      // x fp16
__device__ f16   g_w2 [QKVD  * HID];      // Wq|Wk|Wv fp16
__device__ bf16  g_qs [S_TOK * NH  * 256];// Q split bf16 [S][16][hi128|lo128]
__device__ bf16  g_ks [S_TOK * NKV * 256];// K split bf16 [S][8][hi128|lo128]
__device__ float g_v  [S_TOK * NKV * HD]; // V fp32 packed [S][8][128]
__device__ f16   g_vh [S_TOK * NKV * 32]; // V cols 96..127 fp16 [S][8][32]
__device__ f16   g_o2 [S_TOK * OD];       // attn out fp16
__device__ f16   g_wo2[HID * OD];         // Wo fp16

// ---------------- helpers ------------------------------------------------
__device__ __forceinline__ u64 pack2(float a, float b) {
    u64 r; asm("mov.b64 %0,{%1,%2};" : "=l"(r) : "f"(a), "f"(b)); return r;
}
__device__ __forceinline__ void unpack2(u64 v, float& a, float& b) {
    asm("mov.b64 {%0,%1},%2;" : "=f"(a), "=f"(b) : "l"(v));
}
__device__ __forceinline__ void fma2(u64& c, u64 a, u64 b) {
    asm("fma.rn.f32x2 %0,%1,%2,%3;" : "=l"(c) : "l"(a), "l"(b), "l"(c));
}
__device__ __forceinline__ u64 mul2(u64 a, u64 b) {
    u64 r; asm("mul.rn.f32x2 %0,%1,%2;" : "=l"(r) : "l"(a), "l"(b)); return r;
}
__device__ __forceinline__ u32 s2u(const void* p) {
    u32 a; asm("{ .reg .u64 t; cvta.to.shared.u64 t,%1; cvt.u32.u64 %0,t; }"
               : "=r"(a) : "l"(p));
    return a;
}
__device__ __forceinline__ void cp16(u32 dst, const void* src) {
    asm volatile("cp.async.cg.shared.global [%0],[%1],16;" :: "r"(dst), "l"(src));
}
__device__ __forceinline__ void cp_commit() {
    asm volatile("cp.async.commit_group;" ::: "memory");
}
__device__ __forceinline__ void ldsm_x4(u32* r, u32 addr) {
    asm volatile("ldmatrix.sync.aligned.m8n8.x4.shared.b16 {%0,%1,%2,%3},[%4];"
                 : "=r"(r[0]), "=r"(r[1]), "=r"(r[2]), "=r"(r[3]) : "r"(addr));
}
__device__ __forceinline__ void ldsm_x4_t(u32* r, u32 addr) {
    asm volatile("ldmatrix.sync.aligned.m8n8.x4.trans.shared.b16 {%0,%1,%2,%3},[%4];"
                 : "=r"(r[0]), "=r"(r[1]), "=r"(r[2]), "=r"(r[3]) : "r"(addr));
}
__device__ __forceinline__ void mma_bf16(float* d, const u32* a, const u32* b) {
    asm volatile(
        "mma.sync.aligned.m16n8k16.row.col.f32.bf16.bf16.f32 "
        "{%0,%1,%2,%3},{%4,%5,%6,%7},{%8,%9},{%0,%1,%2,%3};"
        : "+f"(d[0]), "+f"(d[1]), "+f"(d[2]), "+f"(d[3])
        : "r"(a[0]), "r"(a[1]), "r"(a[2]), "r"(a[3]), "r"(b[0]), "r"(b[1]));
}
__device__ __forceinline__ void mma_f16(float* d, const u32* a, const u32* b) {
    asm volatile(
        "mma.sync.aligned.m16n8k16.row.col.f32.f16.f16.f32 "
        "{%0,%1,%2,%3},{%4,%5,%6,%7},{%8,%9},{%0,%1,%2,%3};"
        : "+f"(d[0]), "+f"(d[1]), "+f"(d[2]), "+f"(d[3])
        : "r"(a[0]), "r"(a[1]), "r"(a[2]), "r"(a[3]), "r"(b[0]), "r"(b[1]));
}
__device__ __forceinline__ u32 packh2(float a, float b) {
    u32 r; asm("cvt.rn.f16x2.f32 %0,%1,%2;" : "=r"(r) : "f"(b), "f"(a));
    return r;
}

// ---------------------------------------------------------------------------
// merged fp16 conversion: x, Wq, Wk, Wv, Wo in one launch (8 elems/thread)
// grid = 4096 + 1024 + 512 + 512 + 1024 = 7168 blocks
// ---------------------------------------------------------------------------
__global__ __launch_bounds__(256) void cvt_all(
    const float* __restrict__ x,  const float* __restrict__ Wq,
    const float* __restrict__ Wk, const float* __restrict__ Wv,
    const float* __restrict__ Wo,
    f16* __restrict__ x2, f16* __restrict__ w2, f16* __restrict__ wo2)
{
    int b = blockIdx.x;
    const float* src; f16* dst; int base;
    if (b < 4096)      { src = x;  dst = x2;                          base = b; }
    else if (b < 5120) { src = Wq; dst = w2;                          base = b - 4096; }
    else if (b < 5632) { src = Wk; dst = w2 + (size_t)2048 * HID;     base = b - 5120; }
    else if (b < 6144) { src = Wv; dst = w2 + (size_t)3072 * HID;     base = b - 5632; }
    else               { src = Wo; dst = wo2;                         base = b - 6144; }
    size_t i = ((size_t)base * 256 + threadIdx.x) * 8;
    float4 v0 = *(const float4*)(src + i);
    float4 v1 = *(const float4*)(src + i + 4);
    uint4 o;
    o.x = packh2(v0.x, v0.y); o.y = packh2(v0.z, v0.w);
    o.z = packh2(v1.x, v1.y); o.w = packh2(v1.z, v1.w);
    *(uint4*)(dst + i) = o;
}

// ---------------------------------------------------------------------------
// mma.sync GEMM (proven mainloop): C = A[M,Kp] f16 @ B[N,Kp]^T f16
// fuse==0: plain fp32 epilogue. fuse==1: QKV epilogue (norm+rope / V stores).
// ---------------------------------------------------------------------------
#define GSTAGE 32768
#define GEMM_SMEM (3 * GSTAGE)

__global__ __launch_bounds__(256) void gemm_mma(
    const f16* __restrict__ A, const f16* __restrict__ B,
    float* __restrict__ C, int N, int Kp, int fuse,
    bf16* __restrict__ qs, bf16* __restrict__ ks,
    float* __restrict__ vout, f16* __restrict__ vhout,
    const float* __restrict__ cosT, const float* __restrict__ sinT,
    const float* __restrict__ qw, const float* __restrict__ kw)
{
    extern __shared__ char smc[];
    const u32 smb = s2u(smc);
    const int tid = threadIdx.x;
    const int warp = tid >> 5, lane = tid & 31;
    const int wM = warp >> 2, wN = warp & 3;
    const int m0 = blockIdx.y << 7, n0 = blockIdx.x << 7;
    const int chunks = Kp >> 6;

    const f16* Ag = A + (size_t)m0 * Kp;
    const f16* Bg = B + (size_t)n0 * Kp;

    float acc[4][4][4];
#pragma unroll
    for (int a = 0; a < 4; a++)
#pragma unroll
        for (int b = 0; b < 4; b++)
#pragma unroll
            for (int c = 0; c < 4; c++) acc[a][b][c] = 0.f;

    auto load_stage = [&](int st, int ch) {
        u32 sa = smb + st * GSTAGE;
        u32 sb = sa + 16384;
#pragma unroll
        for (int j = 0; j < 4; j++) {
            int q = tid + j * 256;
            int r = q >> 3, c = q & 7;
            cp16(sa + r * 128 + ((c ^ (r & 7)) << 4),
                 Ag + (size_t)r * Kp + ch * 64 + c * 8);
        }
#pragma unroll
        for (int j = 0; j < 4; j++) {
            int q = tid + j * 256;
            int r = q >> 3, c = q & 7;
            cp16(sb + r * 128 + ((c ^ (r & 7)) << 4),
                 Bg + (size_t)r * Kp + ch * 64 + c * 8);
        }
        cp_commit();
    };

    load_stage(0, 0);
    load_stage(1, 1);

    for (int i = 0; i < chunks; i++) {
        int s = i % 3;
        asm volatile("cp.async.wait_group 1;" ::: "memory");
        __syncthreads();
        if (i + 2 < chunks) load_stage((i + 2) % 3, i + 2);
        else cp_commit();

        u32 sa = smb + s * GSTAGE;
        u32 sb = sa + 16384;
#pragma unroll
        for (int kk = 0; kk < 4; kk++) {
            u32 afr[4][4], bfr[2][4];
#pragma unroll
            for (int mt = 0; mt < 4; mt++) {
                int row = wM * 64 + mt * 16 + (lane & 15);
                int ch = kk * 2 + (lane >> 4);
                ldsm_x4(afr[mt], sa + row * 128 + ((ch ^ (row & 7)) << 4));
            }
#pragma unroll
            for (int p = 0; p < 2; p++) {
                int row = wN * 32 + p * 16 + ((lane >> 4) << 3) + (lane & 7);
                int ch = kk * 2 + ((lane >> 3) & 1);
                ldsm_x4(bfr[p], sb + row * 128 + ((ch ^ (row & 7)) << 4));
            }
#pragma unroll
            for (int mt = 0; mt < 4; mt++)
#pragma unroll
                for (int nt = 0; nt < 4; nt++)
                    mma_f16(acc[mt][nt], afr[mt], &bfr[nt >> 1][(nt & 1) * 2]);
        }
    }

    const int g = lane >> 2, t = lane & 3;

    if (!fuse) {
#pragma unroll
        for (int mt = 0; mt < 4; mt++) {
            int r0 = m0 + wM * 64 + mt * 16 + g;
#pragma unroll
            for (int nt = 0; nt < 4; nt++) {
                int cc = n0 + wN * 32 + nt * 8 + t * 2;
                *(float2*)(C + (size_t)r0 * N + cc) =
                    make_float2(acc[mt][nt][0], acc[mt][nt][1]);
                *(float2*)(C + (size_t)(r0 + 8) * N + cc) =
                    make_float2(acc[mt][nt][2], acc[mt][nt][3]);
            }
        }
        return;
    }

    const int nb = blockIdx.x;   // 0..15 q, 16..23 k, 24..31 v
    if (nb >= 24) {
        int head = nb - 24;
        int vc0 = head * 128;
#pragma unroll
        for (int mt = 0; mt < 4; mt++) {
            int r0 = m0 + wM * 64 + mt * 16 + g;
#pragma unroll
            for (int nt = 0; nt < 4; nt++) {
                int cc = vc0 + wN * 32 + nt * 8 + t * 2;
                *(float2*)(vout + (size_t)r0 * (NKV * HD) + cc) =
                    make_float2(acc[mt][nt][0], acc[mt][nt][1]);
                *(float2*)(vout + (size_t)(r0 + 8) * (NKV * HD) + cc) =
                    make_float2(acc[mt][nt][2], acc[mt][nt][3]);
            }
        }
        if (wN == 3) {   // cols 96..127 -> fp16 copy for tensor-PV slice
#pragma unroll
            for (int mt = 0; mt < 4; mt++) {
                int r0 = m0 + wM * 64 + mt * 16 + g;
#pragma unroll
                for (int nt = 0; nt < 4; nt++) {
                    int sc = nt * 8 + t * 2;
                    *(u32*)(vhout + ((size_t)r0 * NKV + head) * 32 + sc) =
                        packh2(acc[mt][nt][0], acc[mt][nt][1]);
                    *(u32*)(vhout + ((size_t)(r0 + 8) * NKV + head) * 32 + sc) =
                        packh2(acc[mt][nt][2], acc[mt][nt][3]);
                }
            }
        }
        return;
    }

    // q/k block: fused RMSNorm + RoPE (stage tile through smem)
    float* Cs = (float*)smc;
    __syncthreads();
#pragma unroll
    for (int mt = 0; mt < 4; mt++) {
        int rl = wM * 64 + mt * 16 + g;
#pragma unroll
        for (int nt = 0; nt < 4; nt++) {
            int cl = wN * 32 + nt * 8 + t * 2;
            *(float2*)&Cs[rl * 132 + cl]       = make_float2(acc[mt][nt][0], acc[mt][nt][1]);
            *(float2*)&Cs[(rl + 8) * 132 + cl] = make_float2(acc[mt][nt][2], acc[mt][nt][3]);
        }
    }
    __syncthreads();

    const bool isQ = (nb < 16);
    const float* w = isQ ? qw : kw;
    const float4 wv = *(const float4*)(w + lane * 4);
    const float sgn = (lane < 16) ? -1.0f : 1.0f;
    const size_t tstream = (lane < 16) ? (size_t)0 : (size_t)S_TOK * HD;

#pragma unroll 4
    for (int rr = 0; rr < 16; rr++) {
        int row = warp * 16 + rr;
        int s = m0 + row;

        float4 x = *(const float4*)&Cs[row * 132 + lane * 4];
        float ss = x.x * x.x + x.y * x.y + x.z * x.z + x.w * x.w;
#pragma unroll
        for (int m = 16; m > 0; m >>= 1) ss += __shfl_xor_sync(0xffffffffu, ss, m);
        float r = rsqrtf(ss * (1.0f / 128.0f) + 1e-6f);

        float xn0 = x.x * r * wv.x, xn1 = x.y * r * wv.y;
        float xn2 = x.z * r * wv.z, xn3 = x.w * r * wv.w;

        float p0 = __shfl_xor_sync(0xffffffffu, xn0, 16);
        float p1 = __shfl_xor_sync(0xffffffffu, xn1, 16);
        float p2 = __shfl_xor_sync(0xffffffffu, xn2, 16);
        float p3 = __shfl_xor_sync(0xffffffffu, xn3, 16);

        size_t toff = tstream + (size_t)s * HD + lane * 4;
        float4 cv = *(const float4*)(cosT + toff);
        float4 sv = *(const float4*)(sinT + toff);

        float ov[4];
        ov[0] = xn0 * cv.x + sgn * p0 * sv.x;
        ov[1] = xn1 * cv.y + sgn * p1 * sv.y;
        ov[2] = xn2 * cv.z + sgn * p2 * sv.z;
        ov[3] = xn3 * cv.w + sgn * p3 * sv.w;

        u64 hp = 0, lp = 0;
#pragma unroll
        for (int j = 0; j < 4; j++) {
            bf16 hb = __float2bfloat16(ov[j]);
            bf16 lb = __float2bfloat16(ov[j] - __bfloat162float(hb));
            hp |= (u64)(*(unsigned short*)&hb) << (16 * j);
            lp |= (u64)(*(unsigned short*)&lb) << (16 * j);
        }
        bf16* dst = isQ ? (qs + ((size_t)s * NH + nb) * 256)
                        : (ks + ((size_t)s * NKV + (nb - 16)) * 256);
        *(u64*)(dst + lane * 4)       = hp;
        *(u64*)(dst + 128 + lane * 4) = lp;
    }
}

// ---------------------------------------------------------------------------
// Warp-specialized flash attention with hybrid PV (R11/R12-proven).
// Output: plain fp16 [S,2048].
// ---------------------------------------------------------------------------
#define AQS 0
#define AKS 32768
#define AVS 98304
#define APF 163840
#define AAF 198656
#define ALF 199168
#define VSL 199424
#define ATT_SMEM 209664
#define VSTR (NKV * HD)

__global__ __launch_bounds__(256) void attn_tc(
    const bf16* __restrict__ qs, const bf16* __restrict__ ks,
    const float* __restrict__ v, const f16* __restrict__ vh,
    f16* __restrict__ o2)
{
    extern __shared__ char sm[];
    const u32 smb = s2u(sm);
    float* Pf = (float*)(sm + APF);
    float* Af = (float*)(sm + AAF);
    float* Lf = (float*)(sm + ALF);

    const int tid = threadIdx.x;
    const int warp = tid >> 5, lane = tid & 31;
    const bool isS = warp < 4;
    const int qt = blockIdx.x, seg = blockIdx.y, h = blockIdx.z;
    const int hkv = h >> 1;

    const bf16* Qg = qs + ((size_t)(seg * SEGLEN + qt * 64) * NH + h) * 256;
    const bf16* Kg = ks + ((size_t)(seg * SEGLEN) * NKV + hkv) * 256;
    const float* Vg = v + (size_t)(seg * SEGLEN) * VSTR + hkv * HD;
    const f16* Vhg = vh + ((size_t)(seg * SEGLEN) * NKV + hkv) * 32;

#pragma unroll
    for (int j = 0; j < 8; j++) {
        int q = tid + j * 256;
        int r = q >> 5, c = q & 31;
        cp16(smb + AQS + r * 512 + ((c ^ (r & 7)) << 4),
             Qg + (size_t)r * (NH * 256) + c * 8);
    }
    cp_commit();
    if (isS) {
#pragma unroll
        for (int j = 0; j < 16; j++) {
            int q = tid + j * 128;
            int r = q >> 5, c = q & 31;
            cp16(smb + AKS + r * 512 + ((c ^ (r & 7)) << 4),
                 Kg + (size_t)r * (NKV * 256) + c * 8);
        }
#pragma unroll
        for (int j = 0; j < 2; j++) {
            int q = tid + j * 128;
            int r = q >> 2, sg = q & 3;
            cp16(smb + VSL + r * 80 + sg * 16,
                 Vhg + (size_t)r * (NKV * 32) + sg * 8);
        }
        cp_commit();
    } else {
        int vt = tid - 128;
#pragma unroll
        for (int j = 0; j < 16; j++) {
            int q = vt + j * 128;
            int r = q >> 5, c = q & 31;
            cp16(smb + AVS + r * 512 + c * 16, Vg + (size_t)r * VSTR + c * 4);
        }
        cp_commit();
    }

    const int g = lane >> 2, t = lane & 3;
    float m0 = -INFINITY, m1 = -INFINITY, l0 = 0.f, l1 = 0.f;
    float osl[4][4];
#pragma unroll
    for (int n = 0; n < 4; n++)
#pragma unroll
        for (int c = 0; c < 4; c++) osl[n][c] = 0.f;

    u64 O2[8][3];
#pragma unroll
    for (int i = 0; i < 8; i++)
#pragma unroll
        for (int j = 0; j < 3; j++) O2[i][j] = 0ULL;
    const int vt = tid - 128;
    const int tx = vt & 15, ty = vt >> 4;

    for (int it = 0; it <= 16; it++) {
        asm volatile("cp.async.wait_group 0;" ::: "memory");
        __syncthreads();

        if (isS && it < 16) {
            if (it + 1 < 16) {
                u32 kd = smb + AKS + ((it + 1) & 1) * 32768;
#pragma unroll
                for (int j = 0; j < 16; j++) {
                    int q = tid + j * 128;
                    int r = q >> 5, c = q & 31;
                    cp16(kd + r * 512 + ((c ^ (r & 7)) << 4),
                         Kg + (size_t)((it + 1) * 64 + r) * (NKV * 256) + c * 8);
                }
                u32 vsd = smb + VSL + ((it + 1) & 1) * 5120;
#pragma unroll
                for (int j = 0; j < 2; j++) {
                    int q = tid + j * 128;
                    int r = q >> 2, sg = q & 3;
                    cp16(vsd + r * 80 + sg * 16,
                         Vhg + (size_t)((it + 1) * 64 + r) * (NKV * 32) + sg * 8);
                }
                cp_commit();
            }
            u32 kb = smb + AKS + (it & 1) * 32768;
            float acc[8][4];
#pragma unroll
            for (int n = 0; n < 8; n++)
#pragma unroll
                for (int c = 0; c < 4; c++) acc[n][c] = 0.f;

            const int ABASE[3] = {0, 16, 0};
            const int BBASE[3] = {0, 0, 16};
#pragma unroll
            for (int p = 0; p < 3; p++) {
#pragma unroll
                for (int k = 0; k < 8; k++) {
                    u32 afr[4], bfr[4][4];
                    int ar = warp * 16 + (lane & 15);
                    int ac = ABASE[p] + 2 * k + (lane >> 4);
                    ldsm_x4(afr, smb + AQS + ar * 512 + ((ac ^ (ar & 7)) << 4));
#pragma unroll
                    for (int pg = 0; pg < 4; pg++) {
                        int br = pg * 16 + ((lane >> 4) << 3) + (lane & 7);
                        int bc = BBASE[p] + 2 * k + ((lane >> 3) & 1);
                        ldsm_x4(bfr[pg], kb + br * 512 + ((bc ^ (br & 7)) << 4));
                    }
#pragma unroll
                    for (int nt = 0; nt < 8; nt++)
                        mma_bf16(acc[nt], afr, &bfr[nt >> 1][(nt & 1) * 2]);
                }
            }
            float mx0 = -INFINITY, mx1 = -INFINITY;
#pragma unroll
            for (int n = 0; n < 8; n++) {
#pragma unroll
                for (int c = 0; c < 4; c++) acc[n][c] *= SCALE;
                mx0 = fmaxf(mx0, fmaxf(acc[n][0], acc[n][1]));
                mx1 = fmaxf(mx1, fmaxf(acc[n][2], acc[n][3]));
            }
            mx0 = fmaxf(mx0, __shfl_xor_sync(0xffffffffu, mx0, 1));
            mx0 = fmaxf(mx0, __shfl_xor_sync(0xffffffffu, mx0, 2));
            mx1 = fmaxf(mx1, __shfl_xor_sync(0xffffffffu, mx1, 1));
            mx1 = fmaxf(mx1, __shfl_xor_sync(0xffffffffu, mx1, 2));
            float mn0 = fmaxf(m0, mx0), mn1 = fmaxf(m1, mx1);
            float a0 = __expf(m0 - mn0), a1 = __expf(m1 - mn1);
            m0 = mn0; m1 = mn1;
            float s0 = 0.f, s1 = 0.f;
#pragma unroll
            for (int n = 0; n < 8; n++) {
                acc[n][0] = __expf(acc[n][0] - mn0); s0 += acc[n][0];
                acc[n][1] = __expf(acc[n][1] - mn0); s0 += acc[n][1];
                acc[n][2] = __expf(acc[n][2] - mn1); s1 += acc[n][2];
                acc[n][3] = __expf(acc[n][3] - mn1); s1 += acc[n][3];
            }
            s0 += __shfl_xor_sync(0xffffffffu, s0, 1);
            s0 += __shfl_xor_sync(0xffffffffu, s0, 2);
            s1 += __shfl_xor_sync(0xffffffffu, s1, 1);
            s1 += __shfl_xor_sync(0xffffffffu, s1, 2);
            l0 = l0 * a0 + s0;
            l1 = l1 * a1 + s1;

            int r0 = warp * 16 + g, r1 = r0 + 8;
            float* Pb = Pf + (it & 1) * (64 * 68);
#pragma unroll
            for (int n = 0; n < 8; n++) {
                *(float2*)&Pb[r0 * 68 + n * 8 + t * 2] = make_float2(acc[n][0], acc[n][1]);
                *(float2*)&Pb[r1 * 68 + n * 8 + t * 2] = make_float2(acc[n][2], acc[n][3]);
            }
            if (t == 0) {
                Af[(it & 1) * 64 + r0] = a0;
                Af[(it & 1) * 64 + r1] = a1;
                if (it == 15) { Lf[r0] = l0; Lf[r1] = l1; }
            }

            // tensor PV slice: cols 96..127
#pragma unroll
            for (int n = 0; n < 4; n++) {
                osl[n][0] *= a0; osl[n][1] *= a0;
                osl[n][2] *= a1; osl[n][3] *= a1;
            }
            u32 vsb = smb + VSL + (it & 1) * 5120;
#pragma unroll
            for (int kk = 0; kk < 4; kk++) {
                u32 pa[4];
                pa[0] = packh2(acc[2 * kk][0],     acc[2 * kk][1]);
                pa[1] = packh2(acc[2 * kk][2],     acc[2 * kk][3]);
                pa[2] = packh2(acc[2 * kk + 1][0], acc[2 * kk + 1][1]);
                pa[3] = packh2(acc[2 * kk + 1][2], acc[2 * kk + 1][3]);
                u32 vb0[4], vb1[4];
                u32 base = vsb + (kk * 16 + (lane & 15)) * 80 + ((lane >> 4) << 4);
                ldsm_x4_t(vb0, base);
                ldsm_x4_t(vb1, base + 32);
                mma_f16(osl[0], pa, vb0);
                mma_f16(osl[1], pa, vb0 + 2);
                mma_f16(osl[2], pa, vb1);
                mma_f16(osl[3], pa, vb1 + 2);
            }
        }

        if (!isS && it > 0) {
            int j = it - 1;
            if (it < 16) {
                u32 vd = smb + AVS + (it & 1) * 32768;
#pragma unroll
                for (int jj = 0; jj < 16; jj++) {
                    int q = vt + jj * 128;
                    int r = q >> 5, c = q & 31;
                    cp16(vd + r * 512 + c * 16,
                         Vg + (size_t)(it * 64 + r) * VSTR + c * 4);
                }
                cp_commit();
            }
            const float* Pb = Pf + (j & 1) * (64 * 68);
            const char* Vb = sm + AVS + (j & 1) * 32768;
#pragma unroll
            for (int ii = 0; ii < 8; ii++) {
                float a = Af[(j & 1) * 64 + ty * 8 + ii];
                u64 ad = pack2(a, a);
#pragma unroll
                for (int c = 0; c < 3; c++) O2[ii][c] = mul2(O2[ii][c], ad);
            }
#pragma unroll 2
            for (int j4 = 0; j4 < 16; j4++) {
                float pv[8][4];
#pragma unroll
                for (int ii = 0; ii < 8; ii++) {
                    float4 tmp = *(const float4*)&Pb[(ty * 8 + ii) * 68 + j4 * 4];
                    pv[ii][0] = tmp.x; pv[ii][1] = tmp.y;
                    pv[ii][2] = tmp.z; pv[ii][3] = tmp.w;
                }
#pragma unroll
                for (int e = 0; e < 4; e++) {
                    const u64* vr = (const u64*)(Vb + ((j4 * 4 + e) * 128 + tx * 6) * 4);
                    u64 v0 = vr[0], v1 = vr[1], v2 = vr[2];
#pragma unroll
                    for (int ii = 0; ii < 8; ii++) {
                        u64 pd = pack2(pv[ii][e], pv[ii][e]);
                        fma2(O2[ii][0], pd, v0);
                        fma2(O2[ii][1], pd, v1);
                        fma2(O2[ii][2], pd, v2);
                    }
                }
            }
        }
    }

    if (isS) {
        float inv0 = 1.0f / l0, inv1 = 1.0f / l1;
        int gr0 = seg * SEGLEN + qt * 64 + warp * 16 + g;
#pragma unroll
        for (int n = 0; n < 4; n++) {
            int col = h * HD + 96 + n * 8 + t * 2;
            *(u32*)(o2 + (size_t)gr0 * OD + col) =
                packh2(osl[n][0] * inv0, osl[n][1] * inv0);
            *(u32*)(o2 + (size_t)(gr0 + 8) * OD + col) =
                packh2(osl[n][2] * inv1, osl[n][3] * inv1);
        }
    } else {
#pragma unroll
        for (int ii = 0; ii < 8; ii++) {
            int row = ty * 8 + ii;
            float inv = 1.0f / Lf[row];
            f16* orow = o2 + (size_t)(seg * SEGLEN + qt * 64 + row) * OD + h * HD + tx * 6;
#pragma unroll
            for (int c = 0; c < 3; c++) {
                float lo, hi; unpack2(O2[ii][c], lo, hi);
                *(u32*)(orow + 2 * c) = packh2(lo * inv, hi * inv);
            }
        }
    }
}

// ---------------------------------------------------------------------------
extern "C" void kernel_launch(void* const* d_in, const int* in_sizes, int n_in,
                              void* d_out, int out_size)
{
    const float* x    = (const float*)d_in[0];
    const float* cosT = (const float*)d_in[2];
    const float* sinT = (const float*)d_in[3];
    const float* Wq   = (const float*)d_in[4];
    const float* Wk   = (const float*)d_in[5];
    const float* Wv   = (const float*)d_in[6];
    const float* Wo   = (const float*)d_in[7];
    const float* qw   = (const float*)d_in[8];
    const float* kw   = (const float*)d_in[9];
    float* out = (float*)d_out;

    f16 *x2, *w2, *o2, *wo2, *vhp;
    bf16 *qsp, *ksp;
    float *vp;
    cudaGetSymbolAddress((void**)&x2,  g_x2);
    cudaGetSymbolAddress((void**)&w2,  g_w2);
    cudaGetSymbolAddress((void**)&o2,  g_o2);
    cudaGetSymbolAddress((void**)&wo2, g_wo2);
    cudaGetSymbolAddress((void**)&qsp, g_qs);
    cudaGetSymbolAddress((void**)&ksp, g_ks);
    cudaGetSymbolAddress((void**)&vp,  g_v);
    cudaGetSymbolAddress((void**)&vhp, g_vh);

    cudaFuncSetAttribute(gemm_mma,
        cudaFuncAttributeMaxDynamicSharedMemorySize, GEMM_SMEM);
    cudaFuncSetAttribute(attn_tc,
        cudaFuncAttributeMaxDynamicSharedMemorySize, ATT_SMEM);

    // launch 0: all conversions in one kernel
    cvt_all<<<7168, 256>>>(x, Wq, Wk, Wv, Wo, x2, w2, wo2);

    // launch 1: QKV projection (fp16) with fused RMSNorm+RoPE / V-split epilogue
    gemm_mma<<<dim3(QKVD / 128, S_TOK / 128), 256, GEMM_SMEM>>>(
        x2, w2, nullptr, QKVD, HID, 1, qsp, ksp, vp, vhp, cosT, sinT, qw, kw);

    // launch 2: hybrid attention (R12 config, 64-key chunks) -> fp16 output
    attn_tc<<<dim3(16, 8, 16), 256, ATT_SMEM>>>(qsp, ksp, vp, vhp, o2);

    // launch 3: output projection (fp16) -> d_out
    gemm_mma<<<dim3(HID / 128, S_TOK / 128), 256, GEMM_SMEM>>>(
        o2, wo2, out, HID, OD, 0, nullptr, nullptr, nullptr, nullptr,
        nullptr, nullptr, nullptr, nullptr);
}

// round 15
// speedup vs baseline: 1.2482x; 1.1727x over previous
#include <cuda_runtime.h>
#include <cuda_bf16.h>
#include <cuda_fp16.h>
#include <math.h>
#include <cstdint>

#define S_TOK  8192
#define HID    1024
#define NH     16
#define NKV    8
#define HD     128
#define SEGLEN 1024
#define QKVD   4096
#define OD     2048
#define SCALE  0.08838834764831845f

typedef unsigned long long u64;
typedef unsigned int u32;
typedef __nv_bfloat16 bf16;
typedef __half f16;

// ---------------- scratch -----------------------------------------------
__device__ f16   g_x2 [S_TOK * HID];      // x fp16
__device__ f16   g_w2 [QKVD  * HID];      // Wq|Wk|Wv fp16
__device__ bf16  g_qs [S_TOK * NH  * 256];// Q split bf16 [S][16][hi128|lo128]
__device__ bf16  g_ks [S_TOK * NKV * 256];// K split bf16 [S][8][hi128|lo128]
__device__ float g_v  [S_TOK * NKV * HD]; // V fp32 packed [S][8][128]
__device__ f16   g_vh [S_TOK * NKV * 64]; // V cols 64..127 fp16 [S][8][64]
__device__ f16   g_o2 [S_TOK * OD];       // attn out fp16
__device__ f16   g_wo2[HID * OD];         // Wo fp16

// ---------------- helpers ------------------------------------------------
__device__ __forceinline__ u64 pack2(float a, float b) {
    u64 r; asm("mov.b64 %0,{%1,%2};" : "=l"(r) : "f"(a), "f"(b)); return r;
}
__device__ __forceinline__ void unpack2(u64 v, float& a, float& b) {
    asm("mov.b64 {%0,%1},%2;" : "=f"(a), "=f"(b) : "l"(v));
}
__device__ __forceinline__ void fma2(u64& c, u64 a, u64 b) {
    asm("fma.rn.f32x2 %0,%1,%2,%3;" : "=l"(c) : "l"(a), "l"(b), "l"(c));
}
__device__ __forceinline__ u64 mul2(u64 a, u64 b) {
    u64 r; asm("mul.rn.f32x2 %0,%1,%2;" : "=l"(r) : "l"(a), "l"(b)); return r;
}
__device__ __forceinline__ u32 s2u(const void* p) {
    u32 a; asm("{ .reg .u64 t; cvta.to.shared.u64 t,%1; cvt.u32.u64 %0,t; }"
               : "=r"(a) : "l"(p));
    return a;
}
__device__ __forceinline__ void cp16(u32 dst, const void* src) {
    asm volatile("cp.async.cg.shared.global [%0],[%1],16;" :: "r"(dst), "l"(src));
}
__device__ __forceinline__ void cp_commit() {
    asm volatile("cp.async.commit_group;" ::: "memory");
}
__device__ __forceinline__ void ldsm_x4(u32* r, u32 addr) {
    asm volatile("ldmatrix.sync.aligned.m8n8.x4.shared.b16 {%0,%1,%2,%3},[%4];"
                 : "=r"(r[0]), "=r"(r[1]), "=r"(r[2]), "=r"(r[3]) : "r"(addr));
}
__device__ __forceinline__ void ldsm_x4_t(u32* r, u32 addr) {
    asm volatile("ldmatrix.sync.aligned.m8n8.x4.trans.shared.b16 {%0,%1,%2,%3},[%4];"
                 : "=r"(r[0]), "=r"(r[1]), "=r"(r[2]), "=r"(r[3]) : "r"(addr));
}
__device__ __forceinline__ void mma_bf16(float* d, const u32* a, const u32* b) {
    asm volatile(
        "mma.sync.aligned.m16n8k16.row.col.f32.bf16.bf16.f32 "
        "{%0,%1,%2,%3},{%4,%5,%6,%7},{%8,%9},{%0,%1,%2,%3};"
        : "+f"(d[0]), "+f"(d[1]), "+f"(d[2]), "+f"(d[3])
        : "r"(a[0]), "r"(a[1]), "r"(a[2]), "r"(a[3]), "r"(b[0]), "r"(b[1]));
}
__device__ __forceinline__ void mma_f16(float* d, const u32* a, const u32* b) {
    asm volatile(
        "mma.sync.aligned.m16n8k16.row.col.f32.f16.f16.f32 "
        "{%0,%1,%2,%3},{%4,%5,%6,%7},{%8,%9},{%0,%1,%2,%3};"
        : "+f"(d[0]), "+f"(d[1]), "+f"(d[2]), "+f"(d[3])
        : "r"(a[0]), "r"(a[1]), "r"(a[2]), "r"(a[3]), "r"(b[0]), "r"(b[1]));
}
__device__ __forceinline__ u32 packh2(float a, float b) {
    u32 r; asm("cvt.rn.f16x2.f32 %0,%1,%2;" : "=r"(r) : "f"(b), "f"(a));
    return r;
}

// tiny no-op kernel: shifts ncu's skip-count so launch #5 = attn_tc
__global__ void noop_mark() {}

// ---------------------------------------------------------------------------
// merged fp16 conversion (R14-proven)
// ---------------------------------------------------------------------------
__global__ __launch_bounds__(256) void cvt_all(
    const float* __restrict__ x,  const float* __restrict__ Wq,
    const float* __restrict__ Wk, const float* __restrict__ Wv,
    const float* __restrict__ Wo,
    f16* __restrict__ x2, f16* __restrict__ w2, f16* __restrict__ wo2)
{
    int b = blockIdx.x;
    const float* src; f16* dst; int base;
    if (b < 4096)      { src = x;  dst = x2;                          base = b; }
    else if (b < 5120) { src = Wq; dst = w2;                          base = b - 4096; }
    else if (b < 5632) { src = Wk; dst = w2 + (size_t)2048 * HID;     base = b - 5120; }
    else if (b < 6144) { src = Wv; dst = w2 + (size_t)3072 * HID;     base = b - 5632; }
    else               { src = Wo; dst = wo2;                         base = b - 6144; }
    size_t i = ((size_t)base * 256 + threadIdx.x) * 8;
    float4 v0 = *(const float4*)(src + i);
    float4 v1 = *(const float4*)(src + i + 4);
    uint4 o;
    o.x = packh2(v0.x, v0.y); o.y = packh2(v0.z, v0.w);
    o.z = packh2(v1.x, v1.y); o.w = packh2(v1.z, v1.w);
    *(uint4*)(dst + i) = o;
}

// ---------------------------------------------------------------------------
// mma.sync GEMM (proven mainloop)
// ---------------------------------------------------------------------------
#define GSTAGE 32768
#define GEMM_SMEM (3 * GSTAGE)

__global__ __launch_bounds__(256) void gemm_mma(
    const f16* __restrict__ A, const f16* __restrict__ B,
    float* __restrict__ C, int N, int Kp, int fuse,
    bf16* __restrict__ qs, bf16* __restrict__ ks,
    float* __restrict__ vout, f16* __restrict__ vhout,
    const float* __restrict__ cosT, const float* __restrict__ sinT,
    const float* __restrict__ qw, const float* __restrict__ kw)
{
    extern __shared__ char smc[];
    const u32 smb = s2u(smc);
    const int tid = threadIdx.x;
    const int warp = tid >> 5, lane = tid & 31;
    const int wM = warp >> 2, wN = warp & 3;
    const int m0 = blockIdx.y << 7, n0 = blockIdx.x << 7;
    const int chunks = Kp >> 6;

    const f16* Ag = A + (size_t)m0 * Kp;
    const f16* Bg = B + (size_t)n0 * Kp;

    float acc[4][4][4];
#pragma unroll
    for (int a = 0; a < 4; a++)
#pragma unroll
        for (int b = 0; b < 4; b++)
#pragma unroll
            for (int c = 0; c < 4; c++) acc[a][b][c] = 0.f;

    auto load_stage = [&](int st, int ch) {
        u32 sa = smb + st * GSTAGE;
        u32 sb = sa + 16384;
#pragma unroll
        for (int j = 0; j < 4; j++) {
            int q = tid + j * 256;
            int r = q >> 3, c = q & 7;
            cp16(sa + r * 128 + ((c ^ (r & 7)) << 4),
                 Ag + (size_t)r * Kp + ch * 64 + c * 8);
        }
#pragma unroll
        for (int j = 0; j < 4; j++) {
            int q = tid + j * 256;
            int r = q >> 3, c = q & 7;
            cp16(sb + r * 128 + ((c ^ (r & 7)) << 4),
                 Bg + (size_t)r * Kp + ch * 64 + c * 8);
        }
        cp_commit();
    };

    load_stage(0, 0);
    load_stage(1, 1);

    for (int i = 0; i < chunks; i++) {
        int s = i % 3;
        asm volatile("cp.async.wait_group 1;" ::: "memory");
        __syncthreads();
        if (i + 2 < chunks) load_stage((i + 2) % 3, i + 2);
        else cp_commit();

        u32 sa = smb + s * GSTAGE;
        u32 sb = sa + 16384;
#pragma unroll
        for (int kk = 0; kk < 4; kk++) {
            u32 afr[4][4], bfr[2][4];
#pragma unroll
            for (int mt = 0; mt < 4; mt++) {
                int row = wM * 64 + mt * 16 + (lane & 15);
                int ch = kk * 2 + (lane >> 4);
                ldsm_x4(afr[mt], sa + row * 128 + ((ch ^ (row & 7)) << 4));
            }
#pragma unroll
            for (int p = 0; p < 2; p++) {
                int row = wN * 32 + p * 16 + ((lane >> 4) << 3) + (lane & 7);
                int ch = kk * 2 + ((lane >> 3) & 1);
                ldsm_x4(bfr[p], sb + row * 128 + ((ch ^ (row & 7)) << 4));
            }
#pragma unroll
            for (int mt = 0; mt < 4; mt++)
#pragma unroll
                for (int nt = 0; nt < 4; nt++)
                    mma_f16(acc[mt][nt], afr[mt], &bfr[nt >> 1][(nt & 1) * 2]);
        }
    }

    const int g = lane >> 2, t = lane & 3;

    if (!fuse) {
#pragma unroll
        for (int mt = 0; mt < 4; mt++) {
            int r0 = m0 + wM * 64 + mt * 16 + g;
#pragma unroll
            for (int nt = 0; nt < 4; nt++) {
                int cc = n0 + wN * 32 + nt * 8 + t * 2;
                *(float2*)(C + (size_t)r0 * N + cc) =
                    make_float2(acc[mt][nt][0], acc[mt][nt][1]);
                *(float2*)(C + (size_t)(r0 + 8) * N + cc) =
                    make_float2(acc[mt][nt][2], acc[mt][nt][3]);
            }
        }
        return;
    }

    const int nb = blockIdx.x;   // 0..15 q, 16..23 k, 24..31 v
    if (nb >= 24) {
        int head = nb - 24;
        int vc0 = head * 128;
#pragma unroll
        for (int mt = 0; mt < 4; mt++) {
            int r0 = m0 + wM * 64 + mt * 16 + g;
#pragma unroll
            for (int nt = 0; nt < 4; nt++) {
                int cc = vc0 + wN * 32 + nt * 8 + t * 2;
                *(float2*)(vout + (size_t)r0 * (NKV * HD) + cc) =
                    make_float2(acc[mt][nt][0], acc[mt][nt][1]);
                *(float2*)(vout + (size_t)(r0 + 8) * (NKV * HD) + cc) =
                    make_float2(acc[mt][nt][2], acc[mt][nt][3]);
            }
        }
        if (wN >= 2) {   // cols 64..127 -> fp16 copy for tensor-PV slice
            int cb = (wN - 2) * 32;
#pragma unroll
            for (int mt = 0; mt < 4; mt++) {
                int r0 = m0 + wM * 64 + mt * 16 + g;
#pragma unroll
                for (int nt = 0; nt < 4; nt++) {
                    int sc = cb + nt * 8 + t * 2;
                    *(u32*)(vhout + ((size_t)r0 * NKV + head) * 64 + sc) =
                        packh2(acc[mt][nt][0], acc[mt][nt][1]);
                    *(u32*)(vhout + ((size_t)(r0 + 8) * NKV + head) * 64 + sc) =
                        packh2(acc[mt][nt][2], acc[mt][nt][3]);
                }
            }
        }
        return;
    }

    // q/k block: fused RMSNorm + RoPE (stage tile through smem)
    float* Cs = (float*)smc;
    __syncthreads();
#pragma unroll
    for (int mt = 0; mt < 4; mt++) {
        int rl = wM * 64 + mt * 16 + g;
#pragma unroll
        for (int nt = 0; nt < 4; nt++) {
            int cl = wN * 32 + nt * 8 + t * 2;
            *(float2*)&Cs[rl * 132 + cl]       = make_float2(acc[mt][nt][0], acc[mt][nt][1]);
            *(float2*)&Cs[(rl + 8) * 132 + cl] = make_float2(acc[mt][nt][2], acc[mt][nt][3]);
        }
    }
    __syncthreads();

    const bool isQ = (nb < 16);
    const float* w = isQ ? qw : kw;
    const float4 wv = *(const float4*)(w + lane * 4);
    const float sgn = (lane < 16) ? -1.0f : 1.0f;
    const size_t tstream = (lane < 16) ? (size_t)0 : (size_t)S_TOK * HD;

#pragma unroll 4
    for (int rr = 0; rr < 16; rr++) {
        int row = warp * 16 + rr;
        int s = m0 + row;

        float4 x = *(const float4*)&Cs[row * 132 + lane * 4];
        float ss = x.x * x.x + x.y * x.y + x.z * x.z + x.w * x.w;
#pragma unroll
        for (int m = 16; m > 0; m >>= 1) ss += __shfl_xor_sync(0xffffffffu, ss, m);
        float r = rsqrtf(ss * (1.0f / 128.0f) + 1e-6f);

        float xn0 = x.x * r * wv.x, xn1 = x.y * r * wv.y;
        float xn2 = x.z * r * wv.z, xn3 = x.w * r * wv.w;

        float p0 = __shfl_xor_sync(0xffffffffu, xn0, 16);
        float p1 = __shfl_xor_sync(0xffffffffu, xn1, 16);
        float p2 = __shfl_xor_sync(0xffffffffu, xn2, 16);
        float p3 = __shfl_xor_sync(0xffffffffu, xn3, 16);

        size_t toff = tstream + (size_t)s * HD + lane * 4;
        float4 cv = *(const float4*)(cosT + toff);
        float4 sv = *(const float4*)(sinT + toff);

        float ov[4];
        ov[0] = xn0 * cv.x + sgn * p0 * sv.x;
        ov[1] = xn1 * cv.y + sgn * p1 * sv.y;
        ov[2] = xn2 * cv.z + sgn * p2 * sv.z;
        ov[3] = xn3 * cv.w + sgn * p3 * sv.w;

        u64 hp = 0, lp = 0;
#pragma unroll
        for (int j = 0; j < 4; j++) {
            bf16 hb = __float2bfloat16(ov[j]);
            bf16 lb = __float2bfloat16(ov[j] - __bfloat162float(hb));
            hp |= (u64)(*(unsigned short*)&hb) << (16 * j);
            lp |= (u64)(*(unsigned short*)&lb) << (16 * j);
        }
        bf16* dst = isQ ? (qs + ((size_t)s * NH + nb) * 256)
                        : (ks + ((size_t)s * NKV + (nb - 16)) * 256);
        *(u64*)(dst + lane * 4)       = hp;
        *(u64*)(dst + 128 + lane * 4) = lp;
    }
}

// ---------------------------------------------------------------------------
// Warp-specialized hybrid attention, 64/64 PV split.
//   S-warps (0-3): bf16 3-term scores + softmax + fp16 tensor PV (cols 64-127)
//   V-warps (4-7): fp32 f32x2 PV (cols 0-63)
// smem: Q 32K | K 2x32K | V64 2x16K | P(fp32) 2x17K | A/L | VSL 2x9K
// ---------------------------------------------------------------------------
#define AQS 0
#define AKS 32768
#define AVS 98304
#define APF 131072
#define AAF 165888
#define ALF 166400
#define VSL 166912
#define ATT_SMEM 185344
#define VSTR (NKV * HD)

__global__ __launch_bounds__(256) void attn_tc(
    const bf16* __restrict__ qs, const bf16* __restrict__ ks,
    const float* __restrict__ v, const f16* __restrict__ vh,
    f16* __restrict__ o2)
{
    extern __shared__ char sm[];
    const u32 smb = s2u(sm);
    float* Pf = (float*)(sm + APF);
    float* Af = (float*)(sm + AAF);
    float* Lf = (float*)(sm + ALF);

    const int tid = threadIdx.x;
    const int warp = tid >> 5, lane = tid & 31;
    const bool isS = warp < 4;
    const int qt = blockIdx.x, seg = blockIdx.y, h = blockIdx.z;
    const int hkv = h >> 1;

    const bf16* Qg = qs + ((size_t)(seg * SEGLEN + qt * 64) * NH + h) * 256;
    const bf16* Kg = ks + ((size_t)(seg * SEGLEN) * NKV + hkv) * 256;
    const float* Vg = v + (size_t)(seg * SEGLEN) * VSTR + hkv * HD;
    const f16* Vhg = vh + ((size_t)(seg * SEGLEN) * NKV + hkv) * 64;

#pragma unroll
    for (int j = 0; j < 8; j++) {
        int q = tid + j * 256;
        int r = q >> 5, c = q & 31;
        cp16(smb + AQS + r * 512 + ((c ^ (r & 7)) << 4),
             Qg + (size_t)r * (NH * 256) + c * 8);
    }
    cp_commit();
    if (isS) {
#pragma unroll
        for (int j = 0; j < 16; j++) {
            int q = tid + j * 128;
            int r = q >> 5, c = q & 31;
            cp16(smb + AKS + r * 512 + ((c ^ (r & 7)) << 4),
                 Kg + (size_t)r * (NKV * 256) + c * 8);
        }
#pragma unroll
        for (int j = 0; j < 4; j++) {     // VSL chunk 0: 64 rows x 128B
            int q = tid + j * 128;
            int r = q >> 3, sg = q & 7;
            cp16(smb + VSL + r * 144 + sg * 16,
                 Vhg + (size_t)r * (NKV * 64) + sg * 8);
        }
        cp_commit();
    } else {
        int vt = tid - 128;
#pragma unroll
        for (int j = 0; j < 8; j++) {     // V chunk 0: 64 rows x 256B (cols 0..63)
            int q = vt + j * 128;
            int r = q >> 4, c = q & 15;
            cp16(smb + AVS + r * 256 + c * 16, Vg + (size_t)r * VSTR + c * 4);
        }
        cp_commit();
    }

    const int g = lane >> 2, t = lane & 3;
    float m0 = -INFINITY, m1 = -INFINITY, l0 = 0.f, l1 = 0.f;
    float osl[8][4];                       // S tensor-PV acc (cols 64..127)
#pragma unroll
    for (int n = 0; n < 8; n++)
#pragma unroll
        for (int c = 0; c < 4; c++) osl[n][c] = 0.f;

    u64 O2[8][2];                          // V state (cols 0..63)
#pragma unroll
    for (int i = 0; i < 8; i++)
#pragma unroll
        for (int j = 0; j < 2; j++) O2[i][j] = 0ULL;
    const int vt = tid - 128;
    const int tx = vt & 15, ty = vt >> 4;

    for (int it = 0; it <= 16; it++) {
        asm volatile("cp.async.wait_group 0;" ::: "memory");
        __syncthreads();

        if (isS && it < 16) {
            if (it + 1 < 16) {
                u32 kd = smb + AKS + ((it + 1) & 1) * 32768;
#pragma unroll
                for (int j = 0; j < 16; j++) {
                    int q = tid + j * 128;
                    int r = q >> 5, c = q & 31;
                    cp16(kd + r * 512 + ((c ^ (r & 7)) << 4),
                         Kg + (size_t)((it + 1) * 64 + r) * (NKV * 256) + c * 8);
                }
                u32 vsd = smb + VSL + ((it + 1) & 1) * 9216;
#pragma unroll
                for (int j = 0; j < 4; j++) {
                    int q = tid + j * 128;
                    int r = q >> 3, sg = q & 7;
                    cp16(vsd + r * 144 + sg * 16,
                         Vhg + (size_t)((it + 1) * 64 + r) * (NKV * 64) + sg * 8);
                }
                cp_commit();
            }
            u32 kb = smb + AKS + (it & 1) * 32768;
            float acc[8][4];
#pragma unroll
            for (int n = 0; n < 8; n++)
#pragma unroll
                for (int c = 0; c < 4; c++) acc[n][c] = 0.f;

            const int ABASE[3] = {0, 16, 0};
            const int BBASE[3] = {0, 0, 16};
#pragma unroll
            for (int p = 0; p < 3; p++) {
#pragma unroll
                for (int k = 0; k < 8; k++) {
                    u32 afr[4], bfr[4][4];
                    int ar = warp * 16 + (lane & 15);
                    int ac = ABASE[p] + 2 * k + (lane >> 4);
                    ldsm_x4(afr, smb + AQS + ar * 512 + ((ac ^ (ar & 7)) << 4));
#pragma unroll
                    for (int pg = 0; pg < 4; pg++) {
                        int br = pg * 16 + ((lane >> 4) << 3) + (lane & 7);
                        int bc = BBASE[p] + 2 * k + ((lane >> 3) & 1);
                        ldsm_x4(bfr[pg], kb + br * 512 + ((bc ^ (br & 7)) << 4));
                    }
#pragma unroll
                    for (int nt = 0; nt < 8; nt++)
                        mma_bf16(acc[nt], afr, &bfr[nt >> 1][(nt & 1) * 2]);
                }
            }
            float mx0 = -INFINITY, mx1 = -INFINITY;
#pragma unroll
            for (int n = 0; n < 8; n++) {
#pragma unroll
                for (int c = 0; c < 4; c++) acc[n][c] *= SCALE;
                mx0 = fmaxf(mx0, fmaxf(acc[n][0], acc[n][1]));
                mx1 = fmaxf(mx1, fmaxf(acc[n][2], acc[n][3]));
            }
            mx0 = fmaxf(mx0, __shfl_xor_sync(0xffffffffu, mx0, 1));
            mx0 = fmaxf(mx0, __shfl_xor_sync(0xffffffffu, mx0, 2));
            mx1 = fmaxf(mx1, __shfl_xor_sync(0xffffffffu, mx1, 1));
            mx1 = fmaxf(mx1, __shfl_xor_sync(0xffffffffu, mx1, 2));
            float mn0 = fmaxf(m0, mx0), mn1 = fmaxf(m1, mx1);
            float a0 = __expf(m0 - mn0), a1 = __expf(m1 - mn1);
            m0 = mn0; m1 = mn1;
            float s0 = 0.f, s1 = 0.f;
#pragma unroll
            for (int n = 0; n < 8; n++) {
                acc[n][0] = __expf(acc[n][0] - mn0); s0 += acc[n][0];
                acc[n][1] = __expf(acc[n][1] - mn0); s0 += acc[n][1];
                acc[n][2] = __expf(acc[n][2] - mn1); s1 += acc[n][2];
                acc[n][3] = __expf(acc[n][3] - mn1); s1 += acc[n][3];
            }
            s0 += __shfl_xor_sync(0xffffffffu, s0, 1);
            s0 += __shfl_xor_sync(0xffffffffu, s0, 2);
            s1 += __shfl_xor_sync(0xffffffffu, s1, 1);
            s1 += __shfl_xor_sync(0xffffffffu, s1, 2);
            l0 = l0 * a0 + s0;
            l1 = l1 * a1 + s1;

            int r0 = warp * 16 + g, r1 = r0 + 8;
            float* Pb = Pf + (it & 1) * (64 * 68);
#pragma unroll
            for (int n = 0; n < 8; n++) {
                *(float2*)&Pb[r0 * 68 + n * 8 + t * 2] = make_float2(acc[n][0], acc[n][1]);
                *(float2*)&Pb[r1 * 68 + n * 8 + t * 2] = make_float2(acc[n][2], acc[n][3]);
            }
            if (t == 0) {
                Af[(it & 1) * 64 + r0] = a0;
                Af[(it & 1) * 64 + r1] = a1;
                if (it == 15) { Lf[r0] = l0; Lf[r1] = l1; }
            }

            // tensor PV slice: cols 64..127
#pragma unroll
            for (int n = 0; n < 8; n++) {
                osl[n][0] *= a0; osl[n][1] *= a0;
                osl[n][2] *= a1; osl[n][3] *= a1;
            }
            u32 vsb = smb + VSL + (it & 1) * 9216;
#pragma unroll
            for (int kk = 0; kk < 4; kk++) {
                u32 pa[4];
                pa[0] = packh2(acc[2 * kk][0],     acc[2 * kk][1]);
                pa[1] = packh2(acc[2 * kk][2],     acc[2 * kk][3]);
                pa[2] = packh2(acc[2 * kk + 1][0], acc[2 * kk + 1][1]);
                pa[3] = packh2(acc[2 * kk + 1][2], acc[2 * kk + 1][3]);
                u32 base = vsb + (kk * 16 + (lane & 15)) * 144 + ((lane >> 4) << 4);
#pragma unroll
                for (int jb = 0; jb < 4; jb++) {
                    u32 vb[4];
                    ldsm_x4_t(vb, base + jb * 32);
                    mma_f16(osl[2 * jb],     pa, vb);
                    mma_f16(osl[2 * jb + 1], pa, vb + 2);
                }
            }
        }

        if (!isS && it > 0) {
            int j = it - 1;
            if (it < 16) {
                u32 vd = smb + AVS + (it & 1) * 16384;
#pragma unroll
                for (int jj = 0; jj < 8; jj++) {
                    int q = vt + jj * 128;
                    int r = q >> 4, c = q & 15;
                    cp16(vd + r * 256 + c * 16,
                         Vg + (size_t)(it * 64 + r) * VSTR + c * 4);
                }
                cp_commit();
            }
            const float* Pb = Pf + (j & 1) * (64 * 68);
            const char* Vb = sm + AVS + (j & 1) * 16384;
#pragma unroll
            for (int ii = 0; ii < 8; ii++) {
                float a = Af[(j & 1) * 64 + ty * 8 + ii];
                u64 ad = pack2(a, a);
#pragma unroll
                for (int c = 0; c < 2; c++) O2[ii][c] = mul2(O2[ii][c], ad);
            }
#pragma unroll 2
            for (int j4 = 0; j4 < 16; j4++) {
                float pv[8][4];
#pragma unroll
                for (int ii = 0; ii < 8; ii++) {
                    float4 tmp = *(const float4*)&Pb[(ty * 8 + ii) * 68 + j4 * 4];
                    pv[ii][0] = tmp.x; pv[ii][1] = tmp.y;
                    pv[ii][2] = tmp.z; pv[ii][3] = tmp.w;
                }
#pragma unroll
                for (int e = 0; e < 4; e++) {
                    const u64* vr = (const u64*)(Vb + ((j4 * 4 + e) * 64 + tx * 4) * 4);
                    u64 v0 = vr[0], v1 = vr[1];
#pragma unroll
                    for (int ii = 0; ii < 8; ii++) {
                        u64 pd = pack2(pv[ii][e], pv[ii][e]);
                        fma2(O2[ii][0], pd, v0);
                        fma2(O2[ii][1], pd, v1);
                    }
                }
            }
        }
    }

    if (isS) {
        float inv0 = 1.0f / l0, inv1 = 1.0f / l1;
        int gr0 = seg * SEGLEN + qt * 64 + warp * 16 + g;
#pragma unroll
        for (int n = 0; n < 8; n++) {
            int col = h * HD + 64 + n * 8 + t * 2;
            *(u32*)(o2 + (size_t)gr0 * OD + col) =
                packh2(osl[n][0] * inv0, osl[n][1] * inv0);
            *(u32*)(o2 + (size_t)(gr0 + 8) * OD + col) =
                packh2(osl[n][2] * inv1, osl[n][3] * inv1);
        }
    } else {
#pragma unroll
        for (int ii = 0; ii < 8; ii++) {
            int row = ty * 8 + ii;
            float inv = 1.0f / Lf[row];
            f16* orow = o2 + (size_t)(seg * SEGLEN + qt * 64 + row) * OD + h * HD + tx * 4;
#pragma unroll
            for (int c = 0; c < 2; c++) {
                float lo, hi; unpack2(O2[ii][c], lo, hi);
                *(u32*)(orow + 2 * c) = packh2(lo * inv, hi * inv);
            }
        }
    }
}

// ---------------------------------------------------------------------------
extern "C" void kernel_launch(void* const* d_in, const int* in_sizes, int n_in,
                              void* d_out, int out_size)
{
    const float* x    = (const float*)d_in[0];
    const float* cosT = (const float*)d_in[2];
    const float* sinT = (const float*)d_in[3];
    const float* Wq   = (const float*)d_in[4];
    const float* Wk   = (const float*)d_in[5];
    const float* Wv   = (const float*)d_in[6];
    const float* Wo   = (const float*)d_in[7];
    const float* qw   = (const float*)d_in[8];
    const float* kw   = (const float*)d_in[9];
    float* out = (float*)d_out;

    f16 *x2, *w2, *o2, *wo2, *vhp;
    bf16 *qsp, *ksp;
    float *vp;
    cudaGetSymbolAddress((void**)&x2,  g_x2);
    cudaGetSymbolAddress((void**)&w2,  g_w2);
    cudaGetSymbolAddress((void**)&o2,  g_o2);
    cudaGetSymbolAddress((void**)&wo2, g_wo2);
    cudaGetSymbolAddress((void**)&qsp, g_qs);
    cudaGetSymbolAddress((void**)&ksp, g_ks);
    cudaGetSymbolAddress((void**)&vp,  g_v);
    cudaGetSymbolAddress((void**)&vhp, g_vh);

    cudaFuncSetAttribute(gemm_mma,
        cudaFuncAttributeMaxDynamicSharedMemorySize, GEMM_SMEM);
    cudaFuncSetAttribute(attn_tc,
        cudaFuncAttributeMaxDynamicSharedMemorySize, ATT_SMEM);

    // launch 0: conversions
    cvt_all<<<7168, 256>>>(x, Wq, Wk, Wv, Wo, x2, w2, wo2);

    // launch 1: QKV projection with fused RMSNorm+RoPE / V-split epilogue
    gemm_mma<<<dim3(QKVD / 128, S_TOK / 128), 256, GEMM_SMEM>>>(
        x2, w2, nullptr, QKVD, HID, 1, qsp, ksp, vp, vhp, cosT, sinT, qw, kw);

    // launch 2: marker (shifts ncu -s 5 onto attn_tc)
    noop_mark<<<1, 32>>>();

    // launch 3: hybrid attention (64/64 PV split) -> fp16 output
    attn_tc<<<dim3(16, 8, 16), 256, ATT_SMEM>>>(qsp, ksp, vp, vhp, o2);

    // launch 4: output projection -> d_out
    gemm_mma<<<dim3(HID / 128, S_TOK / 128), 256, GEMM_SMEM>>>(
        o2, wo2, out, HID, OD, 0, nullptr, nullptr, nullptr, nullptr,
        nullptr, nullptr, nullptr, nullptr);
}

// round 16
// speedup vs baseline: 1.3097x; 1.0492x over previous
#include <cuda_runtime.h>
#include <cuda_bf16.h>
#include <cuda_fp16.h>
#include <math.h>
#include <cstdint>

#define S_TOK  8192
#define HID    1024
#define NH     16
#define NKV    8
#define HD     128
#define SEGLEN 1024
#define QKVD   4096
#define OD     2048
#define SCALE  0.08838834764831845f

typedef unsigned long long u64;
typedef unsigned int u32;
typedef __nv_bfloat16 bf16;
typedef __half f16;

// ---------------- scratch -----------------------------------------------
__device__ f16   g_x2 [S_TOK * HID];      // x fp16
__device__ f16   g_w2 [QKVD  * HID];      // Wq|Wk|Wv fp16
__device__ bf16  g_qs [S_TOK * NH  * 256];// Q split bf16 [S][16][hi128|lo128]
__device__ bf16  g_ks [S_TOK * NKV * 256];// K split bf16 [S][8][hi128|lo128]
__device__ float g_v  [S_TOK * NKV * HD]; // V fp32 packed [S][8][128]
__device__ f16   g_vh [S_TOK * NKV * 64]; // V cols 64..127 fp16 [S][8][64]
__device__ f16   g_o2 [S_TOK * OD];       // attn out fp16
__device__ f16   g_wo2[HID * OD];         // Wo fp16

// ---------------- helpers ------------------------------------------------
__device__ __forceinline__ u64 pack2(float a, float b) {
    u64 r; asm("mov.b64 %0,{%1,%2};" : "=l"(r) : "f"(a), "f"(b)); return r;
}
__device__ __forceinline__ void unpack2(u64 v, float& a, float& b) {
    asm("mov.b64 {%0,%1},%2;" : "=f"(a), "=f"(b) : "l"(v));
}
__device__ __forceinline__ void fma2(u64& c, u64 a, u64 b) {
    asm("fma.rn.f32x2 %0,%1,%2,%3;" : "=l"(c) : "l"(a), "l"(b), "l"(c));
}
__device__ __forceinline__ u64 mul2(u64 a, u64 b) {
    u64 r; asm("mul.rn.f32x2 %0,%1,%2;" : "=l"(r) : "l"(a), "l"(b)); return r;
}
__device__ __forceinline__ u32 s2u(const void* p) {
    u32 a; asm("{ .reg .u64 t; cvta.to.shared.u64 t,%1; cvt.u32.u64 %0,t; }"
               : "=r"(a) : "l"(p));
    return a;
}
__device__ __forceinline__ void cp16(u32 dst, const void* src) {
    asm volatile("cp.async.cg.shared.global [%0],[%1],16;" :: "r"(dst), "l"(src));
}
__device__ __forceinline__ void cp_commit() {
    asm volatile("cp.async.commit_group;" ::: "memory");
}
__device__ __forceinline__ void cp_wait0() {
    asm volatile("cp.async.wait_group 0;" ::: "memory");
}
__device__ __forceinline__ void bar_sync(int id, int cnt) {
    asm volatile("bar.sync %0, %1;" :: "r"(id), "r"(cnt) : "memory");
}
__device__ __forceinline__ void bar_arrive(int id, int cnt) {
    asm volatile("bar.arrive %0, %1;" :: "r"(id), "r"(cnt) : "memory");
}
__device__ __forceinline__ void ldsm_x4(u32* r, u32 addr) {
    asm volatile("ldmatrix.sync.aligned.m8n8.x4.shared.b16 {%0,%1,%2,%3},[%4];"
                 : "=r"(r[0]), "=r"(r[1]), "=r"(r[2]), "=r"(r[3]) : "r"(addr));
}
__device__ __forceinline__ void ldsm_x4_t(u32* r, u32 addr) {
    asm volatile("ldmatrix.sync.aligned.m8n8.x4.trans.shared.b16 {%0,%1,%2,%3},[%4];"
                 : "=r"(r[0]), "=r"(r[1]), "=r"(r[2]), "=r"(r[3]) : "r"(addr));
}
__device__ __forceinline__ void mma_bf16(float* d, const u32* a, const u32* b) {
    asm volatile(
        "mma.sync.aligned.m16n8k16.row.col.f32.bf16.bf16.f32 "
        "{%0,%1,%2,%3},{%4,%5,%6,%7},{%8,%9},{%0,%1,%2,%3};"
        : "+f"(d[0]), "+f"(d[1]), "+f"(d[2]), "+f"(d[3])
        : "r"(a[0]), "r"(a[1]), "r"(a[2]), "r"(a[3]), "r"(b[0]), "r"(b[1]));
}
__device__ __forceinline__ void mma_f16(float* d, const u32* a, const u32* b) {
    asm volatile(
        "mma.sync.aligned.m16n8k16.row.col.f32.f16.f16.f32 "
        "{%0,%1,%2,%3},{%4,%5,%6,%7},{%8,%9},{%0,%1,%2,%3};"
        : "+f"(d[0]), "+f"(d[1]), "+f"(d[2]), "+f"(d[3])
        : "r"(a[0]), "r"(a[1]), "r"(a[2]), "r"(a[3]), "r"(b[0]), "r"(b[1]));
}
__device__ __forceinline__ u32 packh2(float a, float b) {
    u32 r; asm("cvt.rn.f16x2.f32 %0,%1,%2;" : "=r"(r) : "f"(b), "f"(a));
    return r;
}

// tiny no-op kernel: shifts ncu's skip-count so launch #5 = attn_tc
__global__ void noop_mark() {}

// ---------------------------------------------------------------------------
// merged fp16 conversion (R14-proven)
// ---------------------------------------------------------------------------
__global__ __launch_bounds__(256) void cvt_all(
    const float* __restrict__ x,  const float* __restrict__ Wq,
    const float* __restrict__ Wk, const float* __restrict__ Wv,
    const float* __restrict__ Wo,
    f16* __restrict__ x2, f16* __restrict__ w2, f16* __restrict__ wo2)
{
    int b = blockIdx.x;
    const float* src; f16* dst; int base;
    if (b < 4096)      { src = x;  dst = x2;                          base = b; }
    else if (b < 5120) { src = Wq; dst = w2;                          base = b - 4096; }
    else if (b < 5632) { src = Wk; dst = w2 + (size_t)2048 * HID;     base = b - 5120; }
    else if (b < 6144) { src = Wv; dst = w2 + (size_t)3072 * HID;     base = b - 5632; }
    else               { src = Wo; dst = wo2;                         base = b - 6144; }
    size_t i = ((size_t)base * 256 + threadIdx.x) * 8;
    float4 v0 = *(const float4*)(src + i);
    float4 v1 = *(const float4*)(src + i + 4);
    uint4 o;
    o.x = packh2(v0.x, v0.y); o.y = packh2(v0.z, v0.w);
    o.z = packh2(v1.x, v1.y); o.w = packh2(v1.z, v1.w);
    *(uint4*)(dst + i) = o;
}

// ---------------------------------------------------------------------------
// mma.sync GEMM (proven mainloop)
// ---------------------------------------------------------------------------
#define GSTAGE 32768
#define GEMM_SMEM (3 * GSTAGE)

__global__ __launch_bounds__(256) void gemm_mma(
    const f16* __restrict__ A, const f16* __restrict__ B,
    float* __restrict__ C, int N, int Kp, int fuse,
    bf16* __restrict__ qs, bf16* __restrict__ ks,
    float* __restrict__ vout, f16* __restrict__ vhout,
    const float* __restrict__ cosT, const float* __restrict__ sinT,
    const float* __restrict__ qw, const float* __restrict__ kw)
{
    extern __shared__ char smc[];
    const u32 smb = s2u(smc);
    const int tid = threadIdx.x;
    const int warp = tid >> 5, lane = tid & 31;
    const int wM = warp >> 2, wN = warp & 3;
    const int m0 = blockIdx.y << 7, n0 = blockIdx.x << 7;
    const int chunks = Kp >> 6;

    const f16* Ag = A + (size_t)m0 * Kp;
    const f16* Bg = B + (size_t)n0 * Kp;

    float acc[4][4][4];
#pragma unroll
    for (int a = 0; a < 4; a++)
#pragma unroll
        for (int b = 0; b < 4; b++)
#pragma unroll
            for (int c = 0; c < 4; c++) acc[a][b][c] = 0.f;

    auto load_stage = [&](int st, int ch) {
        u32 sa = smb + st * GSTAGE;
        u32 sb = sa + 16384;
#pragma unroll
        for (int j = 0; j < 4; j++) {
            int q = tid + j * 256;
            int r = q >> 3, c = q & 7;
            cp16(sa + r * 128 + ((c ^ (r & 7)) << 4),
                 Ag + (size_t)r * Kp + ch * 64 + c * 8);
        }
#pragma unroll
        for (int j = 0; j < 4; j++) {
            int q = tid + j * 256;
            int r = q >> 3, c = q & 7;
            cp16(sb + r * 128 + ((c ^ (r & 7)) << 4),
                 Bg + (size_t)r * Kp + ch * 64 + c * 8);
        }
        cp_commit();
    };

    load_stage(0, 0);
    load_stage(1, 1);

    for (int i = 0; i < chunks; i++) {
        int s = i % 3;
        asm volatile("cp.async.wait_group 1;" ::: "memory");
        __syncthreads();
        if (i + 2 < chunks) load_stage((i + 2) % 3, i + 2);
        else cp_commit();

        u32 sa = smb + s * GSTAGE;
        u32 sb = sa + 16384;
#pragma unroll
        for (int kk = 0; kk < 4; kk++) {
            u32 afr[4][4], bfr[2][4];
#pragma unroll
            for (int mt = 0; mt < 4; mt++) {
                int row = wM * 64 + mt * 16 + (lane & 15);
                int ch = kk * 2 + (lane >> 4);
                ldsm_x4(afr[mt], sa + row * 128 + ((ch ^ (row & 7)) << 4));
            }
#pragma unroll
            for (int p = 0; p < 2; p++) {
                int row = wN * 32 + p * 16 + ((lane >> 4) << 3) + (lane & 7);
                int ch = kk * 2 + ((lane >> 3) & 1);
                ldsm_x4(bfr[p], sb + row * 128 + ((ch ^ (row & 7)) << 4));
            }
#pragma unroll
            for (int mt = 0; mt < 4; mt++)
#pragma unroll
                for (int nt = 0; nt < 4; nt++)
                    mma_f16(acc[mt][nt], afr[mt], &bfr[nt >> 1][(nt & 1) * 2]);
        }
    }

    const int g = lane >> 2, t = lane & 3;

    if (!fuse) {
#pragma unroll
        for (int mt = 0; mt < 4; mt++) {
            int r0 = m0 + wM * 64 + mt * 16 + g;
#pragma unroll
            for (int nt = 0; nt < 4; nt++) {
                int cc = n0 + wN * 32 + nt * 8 + t * 2;
                *(float2*)(C + (size_t)r0 * N + cc) =
                    make_float2(acc[mt][nt][0], acc[mt][nt][1]);
                *(float2*)(C + (size_t)(r0 + 8) * N + cc) =
                    make_float2(acc[mt][nt][2], acc[mt][nt][3]);
            }
        }
        return;
    }

    const int nb = blockIdx.x;   // 0..15 q, 16..23 k, 24..31 v
    if (nb >= 24) {
        int head = nb - 24;
        int vc0 = head * 128;
#pragma unroll
        for (int mt = 0; mt < 4; mt++) {
            int r0 = m0 + wM * 64 + mt * 16 + g;
#pragma unroll
            for (int nt = 0; nt < 4; nt++) {
                int cc = vc0 + wN * 32 + nt * 8 + t * 2;
                *(float2*)(vout + (size_t)r0 * (NKV * HD) + cc) =
                    make_float2(acc[mt][nt][0], acc[mt][nt][1]);
                *(float2*)(vout + (size_t)(r0 + 8) * (NKV * HD) + cc) =
                    make_float2(acc[mt][nt][2], acc[mt][nt][3]);
            }
        }
        if (wN >= 2) {   // cols 64..127 -> fp16 copy for tensor-PV slice
            int cb = (wN - 2) * 32;
#pragma unroll
            for (int mt = 0; mt < 4; mt++) {
                int r0 = m0 + wM * 64 + mt * 16 + g;
#pragma unroll
                for (int nt = 0; nt < 4; nt++) {
                    int sc = cb + nt * 8 + t * 2;
                    *(u32*)(vhout + ((size_t)r0 * NKV + head) * 64 + sc) =
                        packh2(acc[mt][nt][0], acc[mt][nt][1]);
                    *(u32*)(vhout + ((size_t)(r0 + 8) * NKV + head) * 64 + sc) =
                        packh2(acc[mt][nt][2], acc[mt][nt][3]);
                }
            }
        }
        return;
    }

    // q/k block: fused RMSNorm + RoPE (stage tile through smem)
    float* Cs = (float*)smc;
    __syncthreads();
#pragma unroll
    for (int mt = 0; mt < 4; mt++) {
        int rl = wM * 64 + mt * 16 + g;
#pragma unroll
        for (int nt = 0; nt < 4; nt++) {
            int cl = wN * 32 + nt * 8 + t * 2;
            *(float2*)&Cs[rl * 132 + cl]       = make_float2(acc[mt][nt][0], acc[mt][nt][1]);
            *(float2*)&Cs[(rl + 8) * 132 + cl] = make_float2(acc[mt][nt][2], acc[mt][nt][3]);
        }
    }
    __syncthreads();

    const bool isQ = (nb < 16);
    const float* w = isQ ? qw : kw;
    const float4 wv = *(const float4*)(w + lane * 4);
    const float sgn = (lane < 16) ? -1.0f : 1.0f;
    const size_t tstream = (lane < 16) ? (size_t)0 : (size_t)S_TOK * HD;

#pragma unroll 4
    for (int rr = 0; rr < 16; rr++) {
        int row = warp * 16 + rr;
        int s = m0 + row;

        float4 x = *(const float4*)&Cs[row * 132 + lane * 4];
        float ss = x.x * x.x + x.y * x.y + x.z * x.z + x.w * x.w;
#pragma unroll
        for (int m = 16; m > 0; m >>= 1) ss += __shfl_xor_sync(0xffffffffu, ss, m);
        float r = rsqrtf(ss * (1.0f / 128.0f) + 1e-6f);

        float xn0 = x.x * r * wv.x, xn1 = x.y * r * wv.y;
        float xn2 = x.z * r * wv.z, xn3 = x.w * r * wv.w;

        float p0 = __shfl_xor_sync(0xffffffffu, xn0, 16);
        float p1 = __shfl_xor_sync(0xffffffffu, xn1, 16);
        float p2 = __shfl_xor_sync(0xffffffffu, xn2, 16);
        float p3 = __shfl_xor_sync(0xffffffffu, xn3, 16);

        size_t toff = tstream + (size_t)s * HD + lane * 4;
        float4 cv = *(const float4*)(cosT + toff);
        float4 sv = *(const float4*)(sinT + toff);

        float ov[4];
        ov[0] = xn0 * cv.x + sgn * p0 * sv.x;
        ov[1] = xn1 * cv.y + sgn * p1 * sv.y;
        ov[2] = xn2 * cv.z + sgn * p2 * sv.z;
        ov[3] = xn3 * cv.w + sgn * p3 * sv.w;

        u64 hp = 0, lp = 0;
#pragma unroll
        for (int j = 0; j < 4; j++) {
            bf16 hb = __float2bfloat16(ov[j]);
            bf16 lb = __float2bfloat16(ov[j] - __bfloat162float(hb));
            hp |= (u64)(*(unsigned short*)&hb) << (16 * j);
            lp |= (u64)(*(unsigned short*)&lb) << (16 * j);
        }
        bf16* dst = isQ ? (qs + ((size_t)s * NH + nb) * 256)
                        : (ks + ((size_t)s * NKV + (nb - 16)) * 256);
        *(u64*)(dst + lane * 4)       = hp;
        *(u64*)(dst + 128 + lane * 4) = lp;
    }
}

// ---------------------------------------------------------------------------
// Warp-specialized hybrid attention, 64/64 PV split, DECOUPLED roles.
//   S-warps (0-3): scores + softmax + tensor PV (cols 64-127); producer of P.
//   V-warps (4-7): fp32 f32x2 PV (cols 0-63); consumer of P.
// Sync: named barriers. 2+(p): P[p] ready (S arrive, V sync).
//       4+(p): P[p] slot free (V arrive, S sync). 6: S-local. 7: V-local.
// ---------------------------------------------------------------------------
#define AQS 0
#define AKS 32768
#define AVS 98304
#define APF 131072
#define AAF 165888
#define ALF 166400
#define VSL 166912
#define ATT_SMEM 185344
#define VSTR (NKV * HD)

__global__ __launch_bounds__(256) void attn_tc(
    const bf16* __restrict__ qs, const bf16* __restrict__ ks,
    const float* __restrict__ v, const f16* __restrict__ vh,
    f16* __restrict__ o2)
{
    extern __shared__ char sm[];
    const u32 smb = s2u(sm);
    float* Pf = (float*)(sm + APF);
    float* Af = (float*)(sm + AAF);
    float* Lf = (float*)(sm + ALF);

    const int tid = threadIdx.x;
    const int warp = tid >> 5, lane = tid & 31;
    const bool isS = warp < 4;
    const int qt = blockIdx.x, seg = blockIdx.y, h = blockIdx.z;
    const int hkv = h >> 1;

    const bf16* Qg = qs + ((size_t)(seg * SEGLEN + qt * 64) * NH + h) * 256;
    const bf16* Kg = ks + ((size_t)(seg * SEGLEN) * NKV + hkv) * 256;
    const float* Vg = v + (size_t)(seg * SEGLEN) * VSTR + hkv * HD;
    const f16* Vhg = vh + ((size_t)(seg * SEGLEN) * NKV + hkv) * 64;

    const int g = lane >> 2, t = lane & 3;

    if (isS) {
        // ---- S prologue: Q + K0 + VSL0 (S-warps only; V never reads Q) ----
#pragma unroll
        for (int j = 0; j < 16; j++) {
            int q = tid + j * 128;
            int r = q >> 5, c = q & 31;
            cp16(smb + AQS + r * 512 + ((c ^ (r & 7)) << 4),
                 Qg + (size_t)r * (NH * 256) + c * 8);
        }
#pragma unroll
        for (int j = 0; j < 16; j++) {
            int q = tid + j * 128;
            int r = q >> 5, c = q & 31;
            cp16(smb + AKS + r * 512 + ((c ^ (r & 7)) << 4),
                 Kg + (size_t)r * (NKV * 256) + c * 8);
        }
#pragma unroll
        for (int j = 0; j < 4; j++) {
            int q = tid + j * 128;
            int r = q >> 3, sg = q & 7;
            cp16(smb + VSL + r * 144 + sg * 16,
                 Vhg + (size_t)r * (NKV * 64) + sg * 8);
        }
        cp_commit();

        float m0 = -INFINITY, m1 = -INFINITY, l0 = 0.f, l1 = 0.f;
        float osl[8][4];
#pragma unroll
        for (int n = 0; n < 8; n++)
#pragma unroll
            for (int c = 0; c < 4; c++) osl[n][c] = 0.f;

        for (int it = 0; it < 16; it++) {
            cp_wait0();
            bar_sync(6, 128);                 // K[it],VSL[it] visible S-wide
            if (it + 1 < 16) {                // prefetch next K / VSL
                u32 kd = smb + AKS + ((it + 1) & 1) * 32768;
#pragma unroll
                for (int j = 0; j < 16; j++) {
                    int q = tid + j * 128;
                    int r = q >> 5, c = q & 31;
                    cp16(kd + r * 512 + ((c ^ (r & 7)) << 4),
                         Kg + (size_t)((it + 1) * 64 + r) * (NKV * 256) + c * 8);
                }
                u32 vsd = smb + VSL + ((it + 1) & 1) * 9216;
#pragma unroll
                for (int j = 0; j < 4; j++) {
                    int q = tid + j * 128;
                    int r = q >> 3, sg = q & 7;
                    cp16(vsd + r * 144 + sg * 16,
                         Vhg + (size_t)((it + 1) * 64 + r) * (NKV * 64) + sg * 8);
                }
                cp_commit();
            }

            u32 kb = smb + AKS + (it & 1) * 32768;
            float acc[8][4];
#pragma unroll
            for (int n = 0; n < 8; n++)
#pragma unroll
                for (int c = 0; c < 4; c++) acc[n][c] = 0.f;

            const int ABASE[3] = {0, 16, 0};
            const int BBASE[3] = {0, 0, 16};
#pragma unroll
            for (int p = 0; p < 3; p++) {
#pragma unroll
                for (int k = 0; k < 8; k++) {
                    u32 afr[4], bfr[4][4];
                    int ar = warp * 16 + (lane & 15);
                    int ac = ABASE[p] + 2 * k + (lane >> 4);
                    ldsm_x4(afr, smb + AQS + ar * 512 + ((ac ^ (ar & 7)) << 4));
#pragma unroll
                    for (int pg = 0; pg < 4; pg++) {
                        int br = pg * 16 + ((lane >> 4) << 3) + (lane & 7);
                        int bc = BBASE[p] + 2 * k + ((lane >> 3) & 1);
                        ldsm_x4(bfr[pg], kb + br * 512 + ((bc ^ (br & 7)) << 4));
                    }
#pragma unroll
                    for (int nt = 0; nt < 8; nt++)
                        mma_bf16(acc[nt], afr, &bfr[nt >> 1][(nt & 1) * 2]);
                }
            }
            // ---- online softmax ----
            float mx0 = -INFINITY, mx1 = -INFINITY;
#pragma unroll
            for (int n = 0; n < 8; n++) {
#pragma unroll
                for (int c = 0; c < 4; c++) acc[n][c] *= SCALE;
                mx0 = fmaxf(mx0, fmaxf(acc[n][0], acc[n][1]));
                mx1 = fmaxf(mx1, fmaxf(acc[n][2], acc[n][3]));
            }
            mx0 = fmaxf(mx0, __shfl_xor_sync(0xffffffffu, mx0, 1));
            mx0 = fmaxf(mx0, __shfl_xor_sync(0xffffffffu, mx0, 2));
            mx1 = fmaxf(mx1, __shfl_xor_sync(0xffffffffu, mx1, 1));
            mx1 = fmaxf(mx1, __shfl_xor_sync(0xffffffffu, mx1, 2));
            float mn0 = fmaxf(m0, mx0), mn1 = fmaxf(m1, mx1);
            float a0 = __expf(m0 - mn0), a1 = __expf(m1 - mn1);
            m0 = mn0; m1 = mn1;
            float s0 = 0.f, s1 = 0.f;
#pragma unroll
            for (int n = 0; n < 8; n++) {
                acc[n][0] = __expf(acc[n][0] - mn0); s0 += acc[n][0];
                acc[n][1] = __expf(acc[n][1] - mn0); s0 += acc[n][1];
                acc[n][2] = __expf(acc[n][2] - mn1); s1 += acc[n][2];
                acc[n][3] = __expf(acc[n][3] - mn1); s1 += acc[n][3];
            }
            s0 += __shfl_xor_sync(0xffffffffu, s0, 1);
            s0 += __shfl_xor_sync(0xffffffffu, s0, 2);
            s1 += __shfl_xor_sync(0xffffffffu, s1, 1);
            s1 += __shfl_xor_sync(0xffffffffu, s1, 2);
            l0 = l0 * a0 + s0;
            l1 = l1 * a1 + s1;

            // ---- publish P / alpha (wait for consumers to free the slot) ----
            if (it >= 2) bar_sync(4 + (it & 1), 256);
            int r0 = warp * 16 + g, r1 = r0 + 8;
            float* Pb = Pf + (it & 1) * (64 * 68);
#pragma unroll
            for (int n = 0; n < 8; n++) {
                *(float2*)&Pb[r0 * 68 + n * 8 + t * 2] = make_float2(acc[n][0], acc[n][1]);
                *(float2*)&Pb[r1 * 68 + n * 8 + t * 2] = make_float2(acc[n][2], acc[n][3]);
            }
            if (t == 0) {
                Af[(it & 1) * 64 + r0] = a0;
                Af[(it & 1) * 64 + r1] = a1;
                if (it == 15) { Lf[r0] = l0; Lf[r1] = l1; }
            }
            asm volatile("membar.cta;" ::: "memory");
            bar_arrive(2 + (it & 1), 256);

            // ---- tensor PV slice: cols 64..127 ----
#pragma unroll
            for (int n = 0; n < 8; n++) {
                osl[n][0] *= a0; osl[n][1] *= a0;
                osl[n][2] *= a1; osl[n][3] *= a1;
            }
            u32 vsb = smb + VSL + (it & 1) * 9216;
#pragma unroll
            for (int kk = 0; kk < 4; kk++) {
                u32 pa[4];
                pa[0] = packh2(acc[2 * kk][0],     acc[2 * kk][1]);
                pa[1] = packh2(acc[2 * kk][2],     acc[2 * kk][3]);
                pa[2] = packh2(acc[2 * kk + 1][0], acc[2 * kk + 1][1]);
                pa[3] = packh2(acc[2 * kk + 1][2], acc[2 * kk + 1][3]);
                u32 base = vsb + (kk * 16 + (lane & 15)) * 144 + ((lane >> 4) << 4);
#pragma unroll
                for (int jb = 0; jb < 4; jb++) {
                    u32 vb[4];
                    ldsm_x4_t(vb, base + jb * 32);
                    mma_f16(osl[2 * jb],     pa, vb);
                    mma_f16(osl[2 * jb + 1], pa, vb + 2);
                }
            }
        }

        // ---- S epilogue: cols 64..127 ----
        float inv0 = 1.0f / l0, inv1 = 1.0f / l1;
        int gr0 = seg * SEGLEN + qt * 64 + warp * 16 + g;
#pragma unroll
        for (int n = 0; n < 8; n++) {
            int col = h * HD + 64 + n * 8 + t * 2;
            *(u32*)(o2 + (size_t)gr0 * OD + col) =
                packh2(osl[n][0] * inv0, osl[n][1] * inv0);
            *(u32*)(o2 + (size_t)(gr0 + 8) * OD + col) =
                packh2(osl[n][2] * inv1, osl[n][3] * inv1);
        }
    } else {
        // ================= V role =================
        const int vt = tid - 128;
        const int tx = vt & 15, ty = vt >> 4;

        // V prologue: V chunk 0 (cols 0..63)
#pragma unroll
        for (int j = 0; j < 8; j++) {
            int q = vt + j * 128;
            int r = q >> 4, c = q & 15;
            cp16(smb + AVS + r * 256 + c * 16, Vg + (size_t)r * VSTR + c * 4);
        }
        cp_commit();

        u64 O2[8][2];
#pragma unroll
        for (int i = 0; i < 8; i++)
#pragma unroll
            for (int j = 0; j < 2; j++) O2[i][j] = 0ULL;

        for (int it = 0; it < 16; it++) {
            cp_wait0();
            bar_sync(7, 128);                 // V[it] visible V-wide
            if (it + 1 < 16) {                // prefetch next V
                u32 vd = smb + AVS + ((it + 1) & 1) * 16384;
#pragma unroll
                for (int jj = 0; jj < 8; jj++) {
                    int q = vt + jj * 128;
                    int r = q >> 4, c = q & 15;
                    cp16(vd + r * 256 + c * 16,
                         Vg + (size_t)((it + 1) * 64 + r) * VSTR + c * 4);
                }
                cp_commit();
            }

            bar_sync(2 + (it & 1), 256);      // wait P[it] ready
            const float* Pb = Pf + (it & 1) * (64 * 68);
            const char* Vb = sm + AVS + (it & 1) * 16384;
#pragma unroll
            for (int ii = 0; ii < 8; ii++) {
                float a = Af[(it & 1) * 64 + ty * 8 + ii];
                u64 ad = pack2(a, a);
#pragma unroll
                for (int c = 0; c < 2; c++) O2[ii][c] = mul2(O2[ii][c], ad);
            }
#pragma unroll 2
            for (int j4 = 0; j4 < 16; j4++) {
                float pv[8][4];
#pragma unroll
                for (int ii = 0; ii < 8; ii++) {
                    float4 tmp = *(const float4*)&Pb[(ty * 8 + ii) * 68 + j4 * 4];
                    pv[ii][0] = tmp.x; pv[ii][1] = tmp.y;
                    pv[ii][2] = tmp.z; pv[ii][3] = tmp.w;
                }
#pragma unroll
                for (int e = 0; e < 4; e++) {
                    const u64* vr = (const u64*)(Vb + ((j4 * 4 + e) * 64 + tx * 4) * 4);
                    u64 v0 = vr[0], v1 = vr[1];
#pragma unroll
                    for (int ii = 0; ii < 8; ii++) {
                        u64 pd = pack2(pv[ii][e], pv[ii][e]);
                        fma2(O2[ii][0], pd, v0);
                        fma2(O2[ii][1], pd, v1);
                    }
                }
            }
            bar_arrive(4 + (it & 1), 256);    // P slot free
        }

        // ---- V epilogue: cols 0..63 (Lf published with P[15]) ----
#pragma unroll
        for (int ii = 0; ii < 8; ii++) {
            int row = ty * 8 + ii;
            float inv = 1.0f / Lf[row];
            f16* orow = o2 + (size_t)(seg * SEGLEN + qt * 64 + row) * OD + h * HD + tx * 4;
#pragma unroll
            for (int c = 0; c < 2; c++) {
                float lo, hi; unpack2(O2[ii][c], lo, hi);
                *(u32*)(orow + 2 * c) = packh2(lo * inv, hi * inv);
            }
        }
    }
}

// ---------------------------------------------------------------------------
extern "C" void kernel_launch(void* const* d_in, const int* in_sizes, int n_in,
                              void* d_out, int out_size)
{
    const float* x    = (const float*)d_in[0];
    const float* cosT = (const float*)d_in[2];
    const float* sinT = (const float*)d_in[3];
    const float* Wq   = (const float*)d_in[4];
    const float* Wk   = (const float*)d_in[5];
    const float* Wv   = (const float*)d_in[6];
    const float* Wo   = (const float*)d_in[7];
    const float* qw   = (const float*)d_in[8];
    const float* kw   = (const float*)d_in[9];
    float* out = (float*)d_out;

    f16 *x2, *w2, *o2, *wo2, *vhp;
    bf16 *qsp, *ksp;
    float *vp;
    cudaGetSymbolAddress((void**)&x2,  g_x2);
    cudaGetSymbolAddress((void**)&w2,  g_w2);
    cudaGetSymbolAddress((void**)&o2,  g_o2);
    cudaGetSymbolAddress((void**)&wo2, g_wo2);
    cudaGetSymbolAddress((void**)&qsp, g_qs);
    cudaGetSymbolAddress((void**)&ksp, g_ks);
    cudaGetSymbolAddress((void**)&vp,  g_v);
    cudaGetSymbolAddress((void**)&vhp, g_vh);

    cudaFuncSetAttribute(gemm_mma,
        cudaFuncAttributeMaxDynamicSharedMemorySize, GEMM_SMEM);
    cudaFuncSetAttribute(attn_tc,
        cudaFuncAttributeMaxDynamicSharedMemorySize, ATT_SMEM);

    // launch 0: conversions
    cvt_all<<<7168, 256>>>(x, Wq, Wk, Wv, Wo, x2, w2, wo2);

    // launch 1: QKV projection with fused RMSNorm+RoPE / V-split epilogue
    gemm_mma<<<dim3(QKVD / 128, S_TOK / 128), 256, GEMM_SMEM>>>(
        x2, w2, nullptr, QKVD, HID, 1, qsp, ksp, vp, vhp, cosT, sinT, qw, kw);

    // launch 2: marker (keeps ncu -s 5 on attn_tc)
    noop_mark<<<1, 32>>>();

    // launch 3: decoupled hybrid attention -> fp16 output
    attn_tc<<<dim3(16, 8, 16), 256, ATT_SMEM>>>(qsp, ksp, vp, vhp, o2);

    // launch 4: output projection -> d_out
    gemm_mma<<<dim3(HID / 128, S_TOK / 128), 256, GEMM_SMEM>>>(
        o2, wo2, out, HID, OD, 0, nullptr, nullptr, nullptr, nullptr,
        nullptr, nullptr, nullptr, nullptr);
}

// round 17
// speedup vs baseline: 1.9690x; 1.5034x over previous
#include <cuda_runtime.h>
#include <cuda_bf16.h>
#include <cuda_fp16.h>
#include <math.h>
#include <cstdint>

#define S_TOK  8192
#define HID    1024
#define NH     16
#define NKV    8
#define HD     128
#define SEGLEN 1024
#define QKVD   4096
#define OD     2048
#define SCALE  0.08838834764831845f

typedef unsigned long long u64;
typedef unsigned int u32;
typedef __nv_bfloat16 bf16;
typedef __half f16;

// ---------------- scratch -----------------------------------------------
__device__ f16   g_x2 [S_TOK * HID];       // x fp16
__device__ f16   g_w2 [QKVD  * HID];       // Wq|Wk|Wv fp16
__device__ bf16  g_qs [S_TOK * NH  * 256]; // Q split bf16 [S][16][hi128|lo128]
__device__ bf16  g_ks [S_TOK * NKV * 256]; // K split bf16 [S][8][hi128|lo128]
__device__ f16   g_vh [S_TOK * NKV * 128]; // V fp16 [S][8][128]
__device__ f16   g_o2 [S_TOK * OD];        // attn out fp16
__device__ f16   g_wo2[HID * OD];          // Wo fp16

// ---------------- helpers ------------------------------------------------
__device__ __forceinline__ u32 s2u(const void* p) {
    u32 a; asm("{ .reg .u64 t; cvta.to.shared.u64 t,%1; cvt.u32.u64 %0,t; }"
               : "=r"(a) : "l"(p));
    return a;
}
__device__ __forceinline__ void cp16(u32 dst, const void* src) {
    asm volatile("cp.async.cg.shared.global [%0],[%1],16;" :: "r"(dst), "l"(src));
}
__device__ __forceinline__ void cp_commit() {
    asm volatile("cp.async.commit_group;" ::: "memory");
}
__device__ __forceinline__ void cp_wait0() {
    asm volatile("cp.async.wait_group 0;" ::: "memory");
}
__device__ __forceinline__ void ldsm_x4(u32* r, u32 addr) {
    asm volatile("ldmatrix.sync.aligned.m8n8.x4.shared.b16 {%0,%1,%2,%3},[%4];"
                 : "=r"(r[0]), "=r"(r[1]), "=r"(r[2]), "=r"(r[3]) : "r"(addr));
}
__device__ __forceinline__ void ldsm_x4_t(u32* r, u32 addr) {
    asm volatile("ldmatrix.sync.aligned.m8n8.x4.trans.shared.b16 {%0,%1,%2,%3},[%4];"
                 : "=r"(r[0]), "=r"(r[1]), "=r"(r[2]), "=r"(r[3]) : "r"(addr));
}
__device__ __forceinline__ void mma_bf16(float* d, const u32* a, const u32* b) {
    asm volatile(
        "mma.sync.aligned.m16n8k16.row.col.f32.bf16.bf16.f32 "
        "{%0,%1,%2,%3},{%4,%5,%6,%7},{%8,%9},{%0,%1,%2,%3};"
        : "+f"(d[0]), "+f"(d[1]), "+f"(d[2]), "+f"(d[3])
        : "r"(a[0]), "r"(a[1]), "r"(a[2]), "r"(a[3]), "r"(b[0]), "r"(b[1]));
}
__device__ __forceinline__ void mma_f16(float* d, const u32* a, const u32* b) {
    asm volatile(
        "mma.sync.aligned.m16n8k16.row.col.f32.f16.f16.f32 "
        "{%0,%1,%2,%3},{%4,%5,%6,%7},{%8,%9},{%0,%1,%2,%3};"
        : "+f"(d[0]), "+f"(d[1]), "+f"(d[2]), "+f"(d[3])
        : "r"(a[0]), "r"(a[1]), "r"(a[2]), "r"(a[3]), "r"(b[0]), "r"(b[1]));
}
__device__ __forceinline__ u32 packh2(float a, float b) {
    u32 r; asm("cvt.rn.f16x2.f32 %0,%1,%2;" : "=r"(r) : "f"(b), "f"(a));
    return r;
}

// tiny no-op kernel: keeps ncu -s 5 on attn_tc
__global__ void noop_mark() {}

// ---------------------------------------------------------------------------
// merged fp16 conversion (proven)
// ---------------------------------------------------------------------------
__global__ __launch_bounds__(256) void cvt_all(
    const float* __restrict__ x,  const float* __restrict__ Wq,
    const float* __restrict__ Wk, const float* __restrict__ Wv,
    const float* __restrict__ Wo,
    f16* __restrict__ x2, f16* __restrict__ w2, f16* __restrict__ wo2)
{
    int b = blockIdx.x;
    const float* src; f16* dst; int base;
    if (b < 4096)      { src = x;  dst = x2;                          base = b; }
    else if (b < 5120) { src = Wq; dst = w2;                          base = b - 4096; }
    else if (b < 5632) { src = Wk; dst = w2 + (size_t)2048 * HID;     base = b - 5120; }
    else if (b < 6144) { src = Wv; dst = w2 + (size_t)3072 * HID;     base = b - 5632; }
    else               { src = Wo; dst = wo2;                         base = b - 6144; }
    size_t i = ((size_t)base * 256 + threadIdx.x) * 8;
    float4 v0 = *(const float4*)(src + i);
    float4 v1 = *(const float4*)(src + i + 4);
    uint4 o;
    o.x = packh2(v0.x, v0.y); o.y = packh2(v0.z, v0.w);
    o.z = packh2(v1.x, v1.y); o.w = packh2(v1.z, v1.w);
    *(uint4*)(dst + i) = o;
}

// ---------------------------------------------------------------------------
// mma.sync GEMM (proven mainloop)
// fuse==0: plain fp32 epilogue. fuse==1: QKV epilogue (norm+rope / V fp16).
// ---------------------------------------------------------------------------
#define GSTAGE 32768
#define GEMM_SMEM (3 * GSTAGE)

__global__ __launch_bounds__(256) void gemm_mma(
    const f16* __restrict__ A, const f16* __restrict__ B,
    float* __restrict__ C, int N, int Kp, int fuse,
    bf16* __restrict__ qs, bf16* __restrict__ ks, f16* __restrict__ vhout,
    const float* __restrict__ cosT, const float* __restrict__ sinT,
    const float* __restrict__ qw, const float* __restrict__ kw)
{
    extern __shared__ char smc[];
    const u32 smb = s2u(smc);
    const int tid = threadIdx.x;
    const int warp = tid >> 5, lane = tid & 31;
    const int wM = warp >> 2, wN = warp & 3;
    const int m0 = blockIdx.y << 7, n0 = blockIdx.x << 7;
    const int chunks = Kp >> 6;

    const f16* Ag = A + (size_t)m0 * Kp;
    const f16* Bg = B + (size_t)n0 * Kp;

    float acc[4][4][4];
#pragma unroll
    for (int a = 0; a < 4; a++)
#pragma unroll
        for (int b = 0; b < 4; b++)
#pragma unroll
            for (int c = 0; c < 4; c++) acc[a][b][c] = 0.f;

    auto load_stage = [&](int st, int ch) {
        u32 sa = smb + st * GSTAGE;
        u32 sb = sa + 16384;
#pragma unroll
        for (int j = 0; j < 4; j++) {
            int q = tid + j * 256;
            int r = q >> 3, c = q & 7;
            cp16(sa + r * 128 + ((c ^ (r & 7)) << 4),
                 Ag + (size_t)r * Kp + ch * 64 + c * 8);
        }
#pragma unroll
        for (int j = 0; j < 4; j++) {
            int q = tid + j * 256;
            int r = q >> 3, c = q & 7;
            cp16(sb + r * 128 + ((c ^ (r & 7)) << 4),
                 Bg + (size_t)r * Kp + ch * 64 + c * 8);
        }
        cp_commit();
    };

    load_stage(0, 0);
    load_stage(1, 1);

    for (int i = 0; i < chunks; i++) {
        int s = i % 3;
        asm volatile("cp.async.wait_group 1;" ::: "memory");
        __syncthreads();
        if (i + 2 < chunks) load_stage((i + 2) % 3, i + 2);
        else cp_commit();

        u32 sa = smb + s * GSTAGE;
        u32 sb = sa + 16384;
#pragma unroll
        for (int kk = 0; kk < 4; kk++) {
            u32 afr[4][4], bfr[2][4];
#pragma unroll
            for (int mt = 0; mt < 4; mt++) {
                int row = wM * 64 + mt * 16 + (lane & 15);
                int ch = kk * 2 + (lane >> 4);
                ldsm_x4(afr[mt], sa + row * 128 + ((ch ^ (row & 7)) << 4));
            }
#pragma unroll
            for (int p = 0; p < 2; p++) {
                int row = wN * 32 + p * 16 + ((lane >> 4) << 3) + (lane & 7);
                int ch = kk * 2 + ((lane >> 3) & 1);
                ldsm_x4(bfr[p], sb + row * 128 + ((ch ^ (row & 7)) << 4));
            }
#pragma unroll
            for (int mt = 0; mt < 4; mt++)
#pragma unroll
                for (int nt = 0; nt < 4; nt++)
                    mma_f16(acc[mt][nt], afr[mt], &bfr[nt >> 1][(nt & 1) * 2]);
        }
    }

    const int g = lane >> 2, t = lane & 3;

    if (!fuse) {
#pragma unroll
        for (int mt = 0; mt < 4; mt++) {
            int r0 = m0 + wM * 64 + mt * 16 + g;
#pragma unroll
            for (int nt = 0; nt < 4; nt++) {
                int cc = n0 + wN * 32 + nt * 8 + t * 2;
                *(float2*)(C + (size_t)r0 * N + cc) =
                    make_float2(acc[mt][nt][0], acc[mt][nt][1]);
                *(float2*)(C + (size_t)(r0 + 8) * N + cc) =
                    make_float2(acc[mt][nt][2], acc[mt][nt][3]);
            }
        }
        return;
    }

    const int nb = blockIdx.x;   // 0..15 q, 16..23 k, 24..31 v
    if (nb >= 24) {
        int head = nb - 24;
#pragma unroll
        for (int mt = 0; mt < 4; mt++) {
            int r0 = m0 + wM * 64 + mt * 16 + g;
#pragma unroll
            for (int nt = 0; nt < 4; nt++) {
                int sc = wN * 32 + nt * 8 + t * 2;
                *(u32*)(vhout + ((size_t)r0 * NKV + head) * 128 + sc) =
                    packh2(acc[mt][nt][0], acc[mt][nt][1]);
                *(u32*)(vhout + ((size_t)(r0 + 8) * NKV + head) * 128 + sc) =
                    packh2(acc[mt][nt][2], acc[mt][nt][3]);
            }
        }
        return;
    }

    // q/k block: fused RMSNorm + RoPE (stage tile through smem)
    float* Cs = (float*)smc;
    __syncthreads();
#pragma unroll
    for (int mt = 0; mt < 4; mt++) {
        int rl = wM * 64 + mt * 16 + g;
#pragma unroll
        for (int nt = 0; nt < 4; nt++) {
            int cl = wN * 32 + nt * 8 + t * 2;
            *(float2*)&Cs[rl * 132 + cl]       = make_float2(acc[mt][nt][0], acc[mt][nt][1]);
            *(float2*)&Cs[(rl + 8) * 132 + cl] = make_float2(acc[mt][nt][2], acc[mt][nt][3]);
        }
    }
    __syncthreads();

    const bool isQ = (nb < 16);
    const float* w = isQ ? qw : kw;
    const float4 wv = *(const float4*)(w + lane * 4);
    const float sgn = (lane < 16) ? -1.0f : 1.0f;
    const size_t tstream = (lane < 16) ? (size_t)0 : (size_t)S_TOK * HD;

#pragma unroll 4
    for (int rr = 0; rr < 16; rr++) {
        int row = warp * 16 + rr;
        int s = m0 + row;

        float4 x = *(const float4*)&Cs[row * 132 + lane * 4];
        float ss = x.x * x.x + x.y * x.y + x.z * x.z + x.w * x.w;
#pragma unroll
        for (int m = 16; m > 0; m >>= 1) ss += __shfl_xor_sync(0xffffffffu, ss, m);
        float r = rsqrtf(ss * (1.0f / 128.0f) + 1e-6f);

        float xn0 = x.x * r * wv.x, xn1 = x.y * r * wv.y;
        float xn2 = x.z * r * wv.z, xn3 = x.w * r * wv.w;

        float p0 = __shfl_xor_sync(0xffffffffu, xn0, 16);
        float p1 = __shfl_xor_sync(0xffffffffu, xn1, 16);
        float p2 = __shfl_xor_sync(0xffffffffu, xn2, 16);
        float p3 = __shfl_xor_sync(0xffffffffu, xn3, 16);

        size_t toff = tstream + (size_t)s * HD + lane * 4;
        float4 cv = *(const float4*)(cosT + toff);
        float4 sv = *(const float4*)(sinT + toff);

        float ov[4];
        ov[0] = xn0 * cv.x + sgn * p0 * sv.x;
        ov[1] = xn1 * cv.y + sgn * p1 * sv.y;
        ov[2] = xn2 * cv.z + sgn * p2 * sv.z;
        ov[3] = xn3 * cv.w + sgn * p3 * sv.w;

        u64 hp = 0, lp = 0;
#pragma unroll
        for (int j = 0; j < 4; j++) {
            bf16 hb = __float2bfloat16(ov[j]);
            bf16 lb = __float2bfloat16(ov[j] - __bfloat162float(hb));
            hp |= (u64)(*(unsigned short*)&hb) << (16 * j);
            lp |= (u64)(*(unsigned short*)&lb) << (16 * j);
        }
        bf16* dst = isQ ? (qs + ((size_t)s * NH + nb) * 256)
                        : (ks + ((size_t)s * NKV + (nb - 16)) * 256);
        *(u64*)(dst + lane * 4)       = hp;
        *(u64*)(dst + 128 + lane * 4) = lp;
    }
}

// ---------------------------------------------------------------------------
// Uniform all-tensor attention: 8 identical warps, 128 q-rows per CTA.
// Each warp: 16 rows -> bf16 3-pass scores, softmax, fp16 PV (P in regs).
// smem: Q 64K | K 2x32K | Vh 2x17K  (no P/alpha/L buffers, no roles)
// ---------------------------------------------------------------------------
#define AQS 0
#define AKS 65536
#define AVH 131072
#define VHSTRIDE 272           // 64 rows x (256B data + 16B pad)
#define ATT_SMEM 165888
#define VSTRH (NKV * 128)

__global__ __launch_bounds__(256) void attn_tc(
    const bf16* __restrict__ qs, const bf16* __restrict__ ks,
    const f16* __restrict__ vh, f16* __restrict__ o2)
{
    extern __shared__ char sm[];
    const u32 smb = s2u(sm);

    const int tid = threadIdx.x;
    const int warp = tid >> 5, lane = tid & 31;
    const int qt = blockIdx.x, seg = blockIdx.y, h = blockIdx.z;
    const int hkv = h >> 1;
    const int g = lane >> 2, t = lane & 3;

    const bf16* Qg = qs + ((size_t)(seg * SEGLEN + qt * 128) * NH + h) * 256;
    const bf16* Kg = ks + ((size_t)(seg * SEGLEN) * NKV + hkv) * 256;
    const f16* Vhg = vh + ((size_t)(seg * SEGLEN) * NKV + hkv) * 128;

    // ---- prologue: Q (128 rows), K chunk0, V chunk0 ----
#pragma unroll
    for (int j = 0; j < 16; j++) {
        int q = tid + j * 256;
        int r = q >> 5, c = q & 31;
        cp16(smb + AQS + r * 512 + ((c ^ (r & 7)) << 4),
             Qg + (size_t)r * (NH * 256) + c * 8);
    }
#pragma unroll
    for (int j = 0; j < 8; j++) {
        int q = tid + j * 256;
        int r = q >> 5, c = q & 31;
        cp16(smb + AKS + r * 512 + ((c ^ (r & 7)) << 4),
             Kg + (size_t)r * (NKV * 256) + c * 8);
    }
#pragma unroll
    for (int j = 0; j < 4; j++) {
        int q = tid + j * 256;
        int r = q >> 4, c = q & 15;
        cp16(smb + AVH + r * VHSTRIDE + c * 16,
             Vhg + (size_t)r * VSTRH + c * 8);
    }
    cp_commit();

    float m0 = -INFINITY, m1 = -INFINITY, l0 = 0.f, l1 = 0.f;
    float Of[16][4];
#pragma unroll
    for (int n = 0; n < 16; n++)
#pragma unroll
        for (int c = 0; c < 4; c++) Of[n][c] = 0.f;

    for (int it = 0; it < 16; it++) {
        cp_wait0();
        __syncthreads();
        if (it + 1 < 16) {
            u32 kd = smb + AKS + ((it + 1) & 1) * 32768;
#pragma unroll
            for (int j = 0; j < 8; j++) {
                int q = tid + j * 256;
                int r = q >> 5, c = q & 31;
                cp16(kd + r * 512 + ((c ^ (r & 7)) << 4),
                     Kg + (size_t)((it + 1) * 64 + r) * (NKV * 256) + c * 8);
            }
            u32 vd = smb + AVH + ((it + 1) & 1) * 17408;
#pragma unroll
            for (int j = 0; j < 4; j++) {
                int q = tid + j * 256;
                int r = q >> 4, c = q & 15;
                cp16(vd + r * VHSTRIDE + c * 16,
                     Vhg + (size_t)((it + 1) * 64 + r) * VSTRH + c * 8);
            }
            cp_commit();
        }

        // ---- scores: 3-pass split-bf16, 16 rows x 64 keys ----
        u32 kb = smb + AKS + (it & 1) * 32768;
        float acc[8][4];
#pragma unroll
        for (int n = 0; n < 8; n++)
#pragma unroll
            for (int c = 0; c < 4; c++) acc[n][c] = 0.f;

        const int ABASE[3] = {0, 16, 0};
        const int BBASE[3] = {0, 0, 16};
#pragma unroll
        for (int p = 0; p < 3; p++) {
#pragma unroll
            for (int k = 0; k < 8; k++) {
                u32 afr[4], bfr[4][4];
                int ar = warp * 16 + (lane & 15);
                int ac = ABASE[p] + 2 * k + (lane >> 4);
                ldsm_x4(afr, smb + AQS + ar * 512 + ((ac ^ (ar & 7)) << 4));
#pragma unroll
                for (int pg = 0; pg < 4; pg++) {
                    int br = pg * 16 + ((lane >> 4) << 3) + (lane & 7);
                    int bc = BBASE[p] + 2 * k + ((lane >> 3) & 1);
                    ldsm_x4(bfr[pg], kb + br * 512 + ((bc ^ (br & 7)) << 4));
                }
#pragma unroll
                for (int nt = 0; nt < 8; nt++)
                    mma_bf16(acc[nt], afr, &bfr[nt >> 1][(nt & 1) * 2]);
            }
        }

        // ---- online softmax (per-warp, rows warp*16+g / +8) ----
        float mx0 = -INFINITY, mx1 = -INFINITY;
#pragma unroll
        for (int n = 0; n < 8; n++) {
#pragma unroll
            for (int c = 0; c < 4; c++) acc[n][c] *= SCALE;
            mx0 = fmaxf(mx0, fmaxf(acc[n][0], acc[n][1]));
            mx1 = fmaxf(mx1, fmaxf(acc[n][2], acc[n][3]));
        }
        mx0 = fmaxf(mx0, __shfl_xor_sync(0xffffffffu, mx0, 1));
        mx0 = fmaxf(mx0, __shfl_xor_sync(0xffffffffu, mx0, 2));
        mx1 = fmaxf(mx1, __shfl_xor_sync(0xffffffffu, mx1, 1));
        mx1 = fmaxf(mx1, __shfl_xor_sync(0xffffffffu, mx1, 2));
        float mn0 = fmaxf(m0, mx0), mn1 = fmaxf(m1, mx1);
        float a0 = __expf(m0 - mn0), a1 = __expf(m1 - mn1);
        m0 = mn0; m1 = mn1;
        float s0 = 0.f, s1 = 0.f;
#pragma unroll
        for (int n = 0; n < 8; n++) {
            acc[n][0] = __expf(acc[n][0] - mn0); s0 += acc[n][0];
            acc[n][1] = __expf(acc[n][1] - mn0); s0 += acc[n][1];
            acc[n][2] = __expf(acc[n][2] - mn1); s1 += acc[n][2];
            acc[n][3] = __expf(acc[n][3] - mn1); s1 += acc[n][3];
        }
        s0 += __shfl_xor_sync(0xffffffffu, s0, 1);
        s0 += __shfl_xor_sync(0xffffffffu, s0, 2);
        s1 += __shfl_xor_sync(0xffffffffu, s1, 1);
        s1 += __shfl_xor_sync(0xffffffffu, s1, 2);
        l0 = l0 * a0 + s0;
        l1 = l1 * a1 + s1;

        // ---- rescale O, then fp16 PV over all 128 columns ----
#pragma unroll
        for (int n = 0; n < 16; n++) {
            Of[n][0] *= a0; Of[n][1] *= a0;
            Of[n][2] *= a1; Of[n][3] *= a1;
        }
        u32 vb_base = smb + AVH + (it & 1) * 17408;
#pragma unroll
        for (int kk = 0; kk < 4; kk++) {
            u32 pa[4];
            pa[0] = packh2(acc[2 * kk][0],     acc[2 * kk][1]);
            pa[1] = packh2(acc[2 * kk][2],     acc[2 * kk][3]);
            pa[2] = packh2(acc[2 * kk + 1][0], acc[2 * kk + 1][1]);
            pa[3] = packh2(acc[2 * kk + 1][2], acc[2 * kk + 1][3]);
            u32 base = vb_base + (kk * 16 + (lane & 15)) * VHSTRIDE
                     + ((lane >> 4) << 4);
#pragma unroll
            for (int jb = 0; jb < 8; jb++) {
                u32 vb[4];
                ldsm_x4_t(vb, base + jb * 32);
                mma_f16(Of[2 * jb],     pa, vb);
                mma_f16(Of[2 * jb + 1], pa, vb + 2);
            }
        }
    }

    // ---- epilogue: 16 rows x 128 cols fp16 ----
    float inv0 = 1.0f / l0, inv1 = 1.0f / l1;
    int gr0 = seg * SEGLEN + qt * 128 + warp * 16 + g;
#pragma unroll
    for (int n = 0; n < 16; n++) {
        int col = h * HD + n * 8 + t * 2;
        *(u32*)(o2 + (size_t)gr0 * OD + col) =
            packh2(Of[n][0] * inv0, Of[n][1] * inv0);
        *(u32*)(o2 + (size_t)(gr0 + 8) * OD + col) =
            packh2(Of[n][2] * inv1, Of[n][3] * inv1);
    }
}

// ---------------------------------------------------------------------------
extern "C" void kernel_launch(void* const* d_in, const int* in_sizes, int n_in,
                              void* d_out, int out_size)
{
    const float* x    = (const float*)d_in[0];
    const float* cosT = (const float*)d_in[2];
    const float* sinT = (const float*)d_in[3];
    const float* Wq   = (const float*)d_in[4];
    const float* Wk   = (const float*)d_in[5];
    const float* Wv   = (const float*)d_in[6];
    const float* Wo   = (const float*)d_in[7];
    const float* qw   = (const float*)d_in[8];
    const float* kw   = (const float*)d_in[9];
    float* out = (float*)d_out;

    f16 *x2, *w2, *o2, *wo2, *vhp;
    bf16 *qsp, *ksp;
    cudaGetSymbolAddress((void**)&x2,  g_x2);
    cudaGetSymbolAddress((void**)&w2,  g_w2);
    cudaGetSymbolAddress((void**)&o2,  g_o2);
    cudaGetSymbolAddress((void**)&wo2, g_wo2);
    cudaGetSymbolAddress((void**)&qsp, g_qs);
    cudaGetSymbolAddress((void**)&ksp, g_ks);
    cudaGetSymbolAddress((void**)&vhp, g_vh);

    cudaFuncSetAttribute(gemm_mma,
        cudaFuncAttributeMaxDynamicSharedMemorySize, GEMM_SMEM);
    cudaFuncSetAttribute(attn_tc,
        cudaFuncAttributeMaxDynamicSharedMemorySize, ATT_SMEM);

    // launch 0: conversions
    cvt_all<<<7168, 256>>>(x, Wq, Wk, Wv, Wo, x2, w2, wo2);

    // launch 1: QKV projection with fused RMSNorm+RoPE / fp16-V epilogue
    gemm_mma<<<dim3(QKVD / 128, S_TOK / 128), 256, GEMM_SMEM>>>(
        x2, w2, nullptr, QKVD, HID, 1, qsp, ksp, vhp, cosT, sinT, qw, kw);

    // launch 2: marker (keeps ncu -s 5 on attn_tc)
    noop_mark<<<1, 32>>>();

    // launch 3: uniform all-tensor attention -> fp16 output
    attn_tc<<<dim3(8, 8, 16), 256, ATT_SMEM>>>(qsp, ksp, vhp, o2);

    // launch 4: output projection -> d_out
    gemm_mma<<<dim3(HID / 128, S_TOK / 128), 256, GEMM_SMEM>>>(
        o2, wo2, out, HID, OD, 0, nullptr, nullptr, nullptr,
        nullptr, nullptr, nullptr, nullptr);
}